// round 12
// baseline (speedup 1.0000x reference)
#include <cuda_runtime.h>
#include <cuda_bf16.h>
#include <math.h>
#include <stdint.h>

#define LNUM 8
#define BB   8
#define TT   1024
#define CC   768
#define HH   12
#define DD   64
#define VV   1024
#define FFF  3072
#define BT   (BB*TT)   // 8192

// ---------------------------------------------------------------------------
// Scratch activations
// ---------------------------------------------------------------------------
__device__ float g_part[2 * BT * CC];          // FFN2 split-K partials
__device__ float g_h  [BT * CC];
__device__ __nv_bfloat16 g_hh [BT * CC];
__device__ __nv_bfloat16 g_hl [BT * CC];
__device__ __nv_bfloat16 g_qvh[BT * 3 * CC];
__device__ __nv_bfloat16 g_qvl[BT * 3 * CC];
__device__ __nv_bfloat16 g_ath[BT * CC];
__device__ __nv_bfloat16 g_atl[BT * CC];
__device__ __nv_bfloat16 g_mih[BT * FFF];
__device__ __nv_bfloat16 g_mil[BT * FFF];

// ---------------------------------------------------------------------------
// Pre-converted weights: transposed [N][K], bf16 hi/lo split
// ---------------------------------------------------------------------------
__device__ __nv_bfloat16 g_wqkv_h[LNUM * 3 * CC * CC];
__device__ __nv_bfloat16 g_wqkv_l[LNUM * 3 * CC * CC];
__device__ __nv_bfloat16 g_w1a_h [LNUM * CC * FFF];
__device__ __nv_bfloat16 g_w1a_l [LNUM * CC * FFF];
__device__ __nv_bfloat16 g_w2a_h [LNUM * CC * FFF];
__device__ __nv_bfloat16 g_w2a_l [LNUM * CC * FFF];
__device__ __nv_bfloat16 g_w1b_h [LNUM * CC * FFF];
__device__ __nv_bfloat16 g_w1b_l [LNUM * CC * FFF];
__device__ __nv_bfloat16 g_w2b_h [LNUM * CC * FFF];
__device__ __nv_bfloat16 g_w2b_l [LNUM * CC * FFF];
__device__ __nv_bfloat16 g_lm_h  [VV * CC];
__device__ __nv_bfloat16 g_lm_l  [VV * CC];

// ---------------------------------------------------------------------------
// Helpers
// ---------------------------------------------------------------------------
__device__ __forceinline__ float gelu_f(float x) {
    return 0.5f * x * (1.0f + erff(x * 0.70710678118654752f));
}

__device__ __forceinline__ uint32_t smem_u32(const void* p) {
    uint32_t a;
    asm("{ .reg .u64 t; cvta.to.shared.u64 t, %1; cvt.u32.u64 %0, t; }"
        : "=r"(a) : "l"(p));
    return a;
}

__device__ __forceinline__ void cpa16(uint32_t s, const void* g) {
    asm volatile("cp.async.cg.shared.global [%0], [%1], 16;"
                 :: "r"(s), "l"(g));
}
#define CP_COMMIT() asm volatile("cp.async.commit_group;" ::: "memory")
#define CP_WAIT1()  asm volatile("cp.async.wait_group 1;" ::: "memory")

__device__ __forceinline__ void ldsm4(uint32_t* r, uint32_t a) {
    asm volatile("ldmatrix.sync.aligned.m8n8.x4.shared.b16 {%0,%1,%2,%3}, [%4];"
        : "=r"(r[0]), "=r"(r[1]), "=r"(r[2]), "=r"(r[3]) : "r"(a));
}
__device__ __forceinline__ void ldsm4t(uint32_t* r, uint32_t a) {
    asm volatile("ldmatrix.sync.aligned.m8n8.x4.trans.shared.b16 {%0,%1,%2,%3}, [%4];"
        : "=r"(r[0]), "=r"(r[1]), "=r"(r[2]), "=r"(r[3]) : "r"(a));
}

__device__ __forceinline__ void mma16816(float* c, const uint32_t* a,
                                         uint32_t b0, uint32_t b1) {
    asm volatile(
        "mma.sync.aligned.m16n8k16.row.col.f32.bf16.bf16.f32 "
        "{%0,%1,%2,%3}, {%4,%5,%6,%7}, {%8,%9}, {%0,%1,%2,%3};"
        : "+f"(c[0]), "+f"(c[1]), "+f"(c[2]), "+f"(c[3])
        : "r"(a[0]), "r"(a[1]), "r"(a[2]), "r"(a[3]), "r"(b0), "r"(b1));
}

__device__ __forceinline__ uint32_t pack_bf2(float a, float b) {
    __nv_bfloat162 p = __floats2bfloat162_rn(a, b);
    return *reinterpret_cast<uint32_t*>(&p);
}
__device__ __forceinline__ void split2(float v0, float v1,
                                       uint32_t& hp, uint32_t& lp) {
    __nv_bfloat16 h0 = __float2bfloat16_rn(v0);
    __nv_bfloat16 h1 = __float2bfloat16_rn(v1);
    float l0 = v0 - __bfloat162float(h0);
    float l1 = v1 - __bfloat162float(h1);
    __nv_bfloat162 hh = __halves2bfloat162(h0, h1);
    hp = *reinterpret_cast<uint32_t*>(&hh);
    lp = pack_bf2(l0, l1);
}

// GEMM smem swizzle: 64B rows, 4 chunks of 16B, chunk ^= (row>>1)&3
__device__ __forceinline__ uint32_t swz(int row, int c) {
    return (uint32_t)((row << 6) + (((c ^ ((row >> 1) & 3)) << 4)));
}
// Attention smem swizzle: 128B rows, 8 chunks of 16B, chunk ^= row&7
__device__ __forceinline__ uint32_t swz8(int row, int c) {
    return (uint32_t)((row << 7) + (((c ^ (row & 7)) << 4)));
}

// ---------------------------------------------------------------------------
// Weight pre-convert
// ---------------------------------------------------------------------------
__device__ __forceinline__ void convert_body(
    const float* __restrict__ Wl, __nv_bfloat16* __restrict__ hl,
    __nv_bfloat16* __restrict__ ll, int K, int N)
{
    __shared__ float t[32][33];
    const int kb = blockIdx.y << 5, nb = blockIdx.x << 5;
    const int tx = threadIdx.x, ty = threadIdx.y;
#pragma unroll
    for (int i = 0; i < 32; i += 8)
        t[ty + i][tx] = Wl[(size_t)(kb + ty + i) * N + nb + tx];
    __syncthreads();
#pragma unroll
    for (int i = 0; i < 32; i += 8) {
        float v = t[tx][ty + i];
        __nv_bfloat16 h = __float2bfloat16_rn(v);
        __nv_bfloat16 l = __float2bfloat16_rn(v - __bfloat162float(h));
        size_t o = (size_t)(nb + ty + i) * K + kb + tx;
        hl[o] = h; ll[o] = l;
    }
}

__global__ void __launch_bounds__(256) convert_w_kernel(
    const float* __restrict__ W, __nv_bfloat16* __restrict__ hi,
    __nv_bfloat16* __restrict__ lo, int K, int N)
{
    const size_t loff = (size_t)blockIdx.z * K * N;
    convert_body(W + loff, hi + loff, lo + loff, K, N);
}

__global__ void __launch_bounds__(256) convert_w2_kernel(
    const float* __restrict__ Wa, const float* __restrict__ Wb,
    __nv_bfloat16* __restrict__ hia, __nv_bfloat16* __restrict__ loa,
    __nv_bfloat16* __restrict__ hib, __nv_bfloat16* __restrict__ lob,
    int K, int N)
{
    int z = blockIdx.z;
    const float* W; __nv_bfloat16 *hi, *lo;
    if (z < LNUM) {
        size_t o = (size_t)z * K * N;
        W = Wa + o; hi = hia + o; lo = loa + o;
    } else {
        size_t o = (size_t)(z - LNUM) * K * N;
        W = Wb + o; hi = hib + o; lo = lob + o;
    }
    convert_body(W, hi, lo, K, N);
}

// ---------------------------------------------------------------------------
// HMMA GEMM S4v3: 128x64 CTA tile, 128 threads (4 warps in M), 3-stage
// pipeline, ONE barrier per k-iter (stage target = buf(kt-1), protected by
// the top-of-loop barrier). 72KB smem -> 3 CTAs/SM.
// NOTE: nk % 3 == 0 holds for all shapes used (24, 48).
// ---------------------------------------------------------------------------
#define TA4 (128 * 64)                  // 8192 B
#define TB4 (64 * 64)                   // 4096 B
#define STG4 (2 * TA4 + 2 * TB4)        // 24576 B
#define SMQ4 (3 * STG4)                 // 73728 B

template<int EPI, int WF32, int WHL>
__global__ void __launch_bounds__(128, 3) hgemm_s4_kernel(
    const __nv_bfloat16* __restrict__ Ah, const __nv_bfloat16* __restrict__ Al,
    const __nv_bfloat16* __restrict__ Bh, const __nv_bfloat16* __restrict__ Bl,
    const float* __restrict__ bias, float* __restrict__ C,
    __nv_bfloat16* __restrict__ Ch, __nv_bfloat16* __restrict__ Cl,
    int N, int K)
{
    extern __shared__ __align__(128) char smem[];
    const int tid  = threadIdx.x;
    const int lane = tid & 31;
    const int wid  = tid >> 5;
    const int g    = lane >> 2, t = lane & 3;
    const int bm   = blockIdx.y << 7, bn = blockIdx.x << 6;
    const uint32_t sbase = smem_u32(smem);

    const __nv_bfloat16* gpA[2] = { Ah + (size_t)bm * K, Al + (size_t)bm * K };
    const __nv_bfloat16* gpB[2] = { Bh + (size_t)bn * K, Bl + (size_t)bn * K };

    float acc[2][8][4];
#pragma unroll
    for (int mi = 0; mi < 2; mi++)
#pragma unroll
        for (int ni = 0; ni < 8; ni++)
#pragma unroll
            for (int r = 0; r < 4; r++) acc[mi][ni][r] = 0.f;

    const int nk = K >> 5;
    const int srow = tid >> 2, schk = tid & 3;

    auto stage = [&](int kt, int buf) {
        uint32_t s0 = sbase + buf * STG4;
        const int kc = kt * 32 + schk * 8;
#pragma unroll
        for (int m = 0; m < 2; m++) {
#pragma unroll
            for (int i = 0; i < 4; i++) {
                int row = srow + i * 32;
                cpa16(s0 + m * TA4 + swz(row, schk),
                      gpA[m] + (size_t)row * K + kc);
            }
#pragma unroll
            for (int i = 0; i < 2; i++) {
                int row = srow + i * 32;
                cpa16(s0 + 2 * TA4 + m * TB4 + swz(row, schk),
                      gpB[m] + (size_t)row * K + kc);
            }
        }
        CP_COMMIT();
    };

    stage(0, 0);
    stage(1, 1);

    const int arow0 = wid * 32 + (lane & 15);
    const int akh   = lane >> 4;
    const int brow0 = (lane & 7) + ((lane >> 4) << 3);
    const int bkh   = (lane >> 3) & 1;

    int buf = 0;
    for (int kt = 0; kt < nk; kt++) {
        CP_WAIT1();
        __syncthreads();

        // stage kt+2 into buf(kt-1) — free: barrier above covers kt-1 reads
        int nbuf = buf + 2; if (nbuf >= 3) nbuf -= 3;
        if (kt + 2 < nk) stage(kt + 2, nbuf); else CP_COMMIT();

        const uint32_t st  = sbase + buf * STG4;
        const uint32_t Ahp = st, Alp = st + TA4;
        const uint32_t Bhp = st + 2 * TA4, Blp = st + 2 * TA4 + TB4;

#pragma unroll
        for (int ks = 0; ks < 2; ks++) {
            uint32_t ah[2][4], al[2][4];
#pragma unroll
            for (int mi = 0; mi < 2; mi++) {
                int row = arow0 + mi * 16;
                uint32_t ao = swz(row, ks * 2 + akh);
                ldsm4(ah[mi], Ahp + ao);
                ldsm4(al[mi], Alp + ao);
            }
#pragma unroll
            for (int nip = 0; nip < 4; nip++) {
                int row = brow0 + nip * 16;
                uint32_t bo = swz(row, ks * 2 + bkh);
                uint32_t bh[4], bl[4];
                ldsm4(bh, Bhp + bo);
                ldsm4(bl, Blp + bo);
#pragma unroll
                for (int mi = 0; mi < 2; mi++) {
                    mma16816(acc[mi][2 * nip],     ah[mi], bh[0], bh[1]);
                    mma16816(acc[mi][2 * nip + 1], ah[mi], bh[2], bh[3]);
                }
#pragma unroll
                for (int mi = 0; mi < 2; mi++) {
                    mma16816(acc[mi][2 * nip],     ah[mi], bl[0], bl[1]);
                    mma16816(acc[mi][2 * nip + 1], ah[mi], bl[2], bl[3]);
                }
#pragma unroll
                for (int mi = 0; mi < 2; mi++) {
                    mma16816(acc[mi][2 * nip],     al[mi], bh[0], bh[1]);
                    mma16816(acc[mi][2 * nip + 1], al[mi], bh[2], bh[3]);
                }
            }
        }
        buf = buf + 1; if (buf == 3) buf = 0;
    }

#pragma unroll
    for (int ni = 0; ni < 8; ni++) {
        int col = bn + ni * 8 + t * 2;
        float b0 = bias[col], b1 = bias[col + 1];
#pragma unroll
        for (int mi = 0; mi < 2; mi++) {
            int r0 = bm + wid * 32 + mi * 16 + g;
            float v0 = acc[mi][ni][0] + b0;
            float v1 = acc[mi][ni][1] + b1;
            float v2 = acc[mi][ni][2] + b0;
            float v3 = acc[mi][ni][3] + b1;
            if (EPI == 1) {
                v0 = gelu_f(v0); v1 = gelu_f(v1);
                v2 = gelu_f(v2); v3 = gelu_f(v3);
            }
            size_t o0 = (size_t)r0 * N + col;
            size_t o1 = (size_t)(r0 + 8) * N + col;
            if (WF32) {
                *(float2*)(C + o0) = make_float2(v0, v1);
                *(float2*)(C + o1) = make_float2(v2, v3);
            }
            if (WHL) {
                uint32_t hp, lp;
                split2(v0, v1, hp, lp);
                *(uint32_t*)(Ch + o0) = hp;
                *(uint32_t*)(Cl + o0) = lp;
                split2(v2, v3, hp, lp);
                *(uint32_t*)(Ch + o1) = hp;
                *(uint32_t*)(Cl + o1) = lp;
            }
        }
    }
}

// ---------------------------------------------------------------------------
// HMMA GEMM S4v3 split-K2 partial (FFN2): z selects K half; raw fp32 out.
// ---------------------------------------------------------------------------
__global__ void __launch_bounds__(128, 3) hgemm_s4_pk_kernel(
    const __nv_bfloat16* __restrict__ Ah, const __nv_bfloat16* __restrict__ Al,
    const __nv_bfloat16* __restrict__ Bh, const __nv_bfloat16* __restrict__ Bl,
    float* __restrict__ P, int M, int N, int K)
{
    extern __shared__ __align__(128) char smem[];
    const int tid  = threadIdx.x;
    const int lane = tid & 31;
    const int wid  = tid >> 5;
    const int g    = lane >> 2, t = lane & 3;
    const int bm   = blockIdx.y << 7, bn = blockIdx.x << 6;
    const int z    = blockIdx.z;
    const int Kh   = K >> 1;
    const int kc0  = z * Kh;
    const uint32_t sbase = smem_u32(smem);

    const __nv_bfloat16* gpA[2] = { Ah + (size_t)bm * K + kc0,
                                    Al + (size_t)bm * K + kc0 };
    const __nv_bfloat16* gpB[2] = { Bh + (size_t)bn * K + kc0,
                                    Bl + (size_t)bn * K + kc0 };

    float acc[2][8][4];
#pragma unroll
    for (int mi = 0; mi < 2; mi++)
#pragma unroll
        for (int ni = 0; ni < 8; ni++)
#pragma unroll
            for (int r = 0; r < 4; r++) acc[mi][ni][r] = 0.f;

    const int nk = Kh >> 5;
    const int srow = tid >> 2, schk = tid & 3;

    auto stage = [&](int kt, int buf) {
        uint32_t s0 = sbase + buf * STG4;
        const int kc = kt * 32 + schk * 8;
#pragma unroll
        for (int m = 0; m < 2; m++) {
#pragma unroll
            for (int i = 0; i < 4; i++) {
                int row = srow + i * 32;
                cpa16(s0 + m * TA4 + swz(row, schk),
                      gpA[m] + (size_t)row * K + kc);
            }
#pragma unroll
            for (int i = 0; i < 2; i++) {
                int row = srow + i * 32;
                cpa16(s0 + 2 * TA4 + m * TB4 + swz(row, schk),
                      gpB[m] + (size_t)row * K + kc);
            }
        }
        CP_COMMIT();
    };

    stage(0, 0);
    stage(1, 1);

    const int arow0 = wid * 32 + (lane & 15);
    const int akh   = lane >> 4;
    const int brow0 = (lane & 7) + ((lane >> 4) << 3);
    const int bkh   = (lane >> 3) & 1;

    int buf = 0;
    for (int kt = 0; kt < nk; kt++) {
        CP_WAIT1();
        __syncthreads();

        int nbuf = buf + 2; if (nbuf >= 3) nbuf -= 3;
        if (kt + 2 < nk) stage(kt + 2, nbuf); else CP_COMMIT();

        const uint32_t st  = sbase + buf * STG4;
        const uint32_t Ahp = st, Alp = st + TA4;
        const uint32_t Bhp = st + 2 * TA4, Blp = st + 2 * TA4 + TB4;

#pragma unroll
        for (int ks = 0; ks < 2; ks++) {
            uint32_t ah[2][4], al[2][4];
#pragma unroll
            for (int mi = 0; mi < 2; mi++) {
                int row = arow0 + mi * 16;
                uint32_t ao = swz(row, ks * 2 + akh);
                ldsm4(ah[mi], Ahp + ao);
                ldsm4(al[mi], Alp + ao);
            }
#pragma unroll
            for (int nip = 0; nip < 4; nip++) {
                int row = brow0 + nip * 16;
                uint32_t bo = swz(row, ks * 2 + bkh);
                uint32_t bh[4], bl[4];
                ldsm4(bh, Bhp + bo);
                ldsm4(bl, Blp + bo);
#pragma unroll
                for (int mi = 0; mi < 2; mi++) {
                    mma16816(acc[mi][2 * nip],     ah[mi], bh[0], bh[1]);
                    mma16816(acc[mi][2 * nip + 1], ah[mi], bh[2], bh[3]);
                }
#pragma unroll
                for (int mi = 0; mi < 2; mi++) {
                    mma16816(acc[mi][2 * nip],     ah[mi], bl[0], bl[1]);
                    mma16816(acc[mi][2 * nip + 1], ah[mi], bl[2], bl[3]);
                }
#pragma unroll
                for (int mi = 0; mi < 2; mi++) {
                    mma16816(acc[mi][2 * nip],     al[mi], bh[0], bh[1]);
                    mma16816(acc[mi][2 * nip + 1], al[mi], bh[2], bh[3]);
                }
            }
        }
        buf = buf + 1; if (buf == 3) buf = 0;
    }

    float* Pz = P + (size_t)z * M * N;
#pragma unroll
    for (int ni = 0; ni < 8; ni++) {
        int col = bn + ni * 8 + t * 2;
#pragma unroll
        for (int mi = 0; mi < 2; mi++) {
            int r0 = bm + wid * 32 + mi * 16 + g;
            *(float2*)(Pz + (size_t)r0 * N + col) =
                make_float2(acc[mi][ni][0], acc[mi][ni][1]);
            *(float2*)(Pz + (size_t)(r0 + 8) * N + col) =
                make_float2(acc[mi][ni][2], acc[mi][ni][3]);
        }
    }
}

// ---------------------------------------------------------------------------
// Embedding
// ---------------------------------------------------------------------------
__global__ void __launch_bounds__(192) embed_kernel(
    const int* __restrict__ x, const float* __restrict__ emb,
    const float* __restrict__ pos, float* __restrict__ h,
    __nv_bfloat16* __restrict__ hh, __nv_bfloat16* __restrict__ hl)
{
    const int bt  = blockIdx.x;
    const int tok = x[bt];
    const int t   = bt & (TT - 1);
    const float4* e4 = (const float4*)(emb + (size_t)tok * CC);
    const float4* p4 = (const float4*)(pos + (size_t)t   * CC);
    const int i = threadIdx.x;
    float4 a = e4[i], b = p4[i];
    float4 s = make_float4(a.x + b.x, a.y + b.y, a.z + b.z, a.w + b.w);
    ((float4*)(h + (size_t)bt * CC))[i] = s;
    size_t o = (size_t)bt * CC + i * 4;
    uint32_t hp, lp;
    split2(s.x, s.y, hp, lp);
    *(uint32_t*)(hh + o) = hp;     *(uint32_t*)(hl + o) = lp;
    split2(s.z, s.w, hp, lp);
    *(uint32_t*)(hh + o + 2) = hp; *(uint32_t*)(hl + o + 2) = lp;
}

// ---------------------------------------------------------------------------
// HMMA flash attention: 64x64 tiles, 4 warps, 64KB smem.
// ---------------------------------------------------------------------------
#define ASMEM (8 * 8192)

__global__ void __launch_bounds__(128) attn_hmma_kernel(
    const __nv_bfloat16* __restrict__ qkvh,
    const __nv_bfloat16* __restrict__ qkvl,
    __nv_bfloat16* __restrict__ outh, __nv_bfloat16* __restrict__ outl)
{
    extern __shared__ __align__(128) char asmem[];
    const int tid  = threadIdx.x;
    const int lane = tid & 31, wid = tid >> 5;
    const int g    = lane >> 2, t = lane & 3;
    const int qtile = blockIdx.x, bh = blockIdx.y;
    const int b = bh / HH, h = bh % HH;
    const int qb = qtile << 6;
    const uint32_t S = smem_u32(asmem);
    const size_t bbase = (size_t)b * TT * 3 * CC;

    auto stage64 = [&](uint32_t off, const __nv_bfloat16* src,
                       int tok0, int coff) {
#pragma unroll
        for (int i = 0; i < 4; i++) {
            int idx = tid + (i << 7);
            int row = idx >> 3, chk = idx & 7;
            const __nv_bfloat16* sp = src + bbase
                + (size_t)(tok0 + row) * (3 * CC) + coff + chk * 8;
            *(uint4*)(asmem + off + swz8(row, chk)) = *(const uint4*)sp;
        }
    };

    stage64(0,    qkvh, qb, CC + h * 64);
    stage64(8192, qkvl, qb, CC + h * 64);
    __syncthreads();

    uint32_t qh[4][4], ql[4][4];
    {
        int row = wid * 16 + (lane & 15);
        int kh  = lane >> 4;
#pragma unroll
        for (int ks = 0; ks < 4; ks++) {
            uint32_t ao = swz8(row, ks * 2 + kh);
            ldsm4(qh[ks], S + 0 + ao);
            ldsm4(ql[ks], S + 8192 + ao);
        }
    }

    float O[8][4];
#pragma unroll
    for (int ni = 0; ni < 8; ni++)
#pragma unroll
        for (int r = 0; r < 4; r++) O[ni][r] = 0.f;
    float m0 = -1e30f, m1 = -1e30f, l0 = 0.f, l1 = 0.f;

    const int row0a = qb + wid * 16 + g;
    const int row1a = row0a + 8;

    for (int kt = 0; kt <= qtile; kt++) {
        const int kb = kt << 6;
        __syncthreads();
        stage64(16384, qkvh, kb, h * 64);
        stage64(24576, qkvl, kb, h * 64);
        stage64(32768, qkvh, kb, 2 * CC + h * 64);
        stage64(40960, qkvl, kb, 2 * CC + h * 64);
        __syncthreads();

        float sa[8][4];
#pragma unroll
        for (int ni = 0; ni < 8; ni++)
#pragma unroll
            for (int r = 0; r < 4; r++) sa[ni][r] = 0.f;
        {
            int brow = (lane & 7) + ((lane >> 4) << 3);
            int bkh  = (lane >> 3) & 1;
#pragma unroll
            for (int ks = 0; ks < 4; ks++) {
#pragma unroll
                for (int nip = 0; nip < 4; nip++) {
                    uint32_t bo = swz8(nip * 16 + brow, ks * 2 + bkh);
                    uint32_t kh_[4], kl_[4];
                    ldsm4(kh_, S + 16384 + bo);
                    ldsm4(kl_, S + 24576 + bo);
                    mma16816(sa[2 * nip],     qh[ks], kh_[0], kh_[1]);
                    mma16816(sa[2 * nip + 1], qh[ks], kh_[2], kh_[3]);
                    mma16816(sa[2 * nip],     qh[ks], kl_[0], kl_[1]);
                    mma16816(sa[2 * nip + 1], qh[ks], kl_[2], kl_[3]);
                    mma16816(sa[2 * nip],     ql[ks], kh_[0], kh_[1]);
                    mma16816(sa[2 * nip + 1], ql[ks], kh_[2], kh_[3]);
                }
            }
        }

        const bool diag = (kt == qtile);
#pragma unroll
        for (int ni = 0; ni < 8; ni++) {
            int c0 = kb + ni * 8 + t * 2, c1 = c0 + 1;
            sa[ni][0] *= 0.125f; sa[ni][1] *= 0.125f;
            sa[ni][2] *= 0.125f; sa[ni][3] *= 0.125f;
            if (diag) {
                if (c0 > row0a) sa[ni][0] = -1e30f;
                if (c1 > row0a) sa[ni][1] = -1e30f;
                if (c0 > row1a) sa[ni][2] = -1e30f;
                if (c1 > row1a) sa[ni][3] = -1e30f;
            }
        }

        float pm0 = -1e30f, pm1 = -1e30f;
#pragma unroll
        for (int ni = 0; ni < 8; ni++) {
            pm0 = fmaxf(pm0, fmaxf(sa[ni][0], sa[ni][1]));
            pm1 = fmaxf(pm1, fmaxf(sa[ni][2], sa[ni][3]));
        }
#pragma unroll
        for (int o = 1; o < 4; o <<= 1) {
            pm0 = fmaxf(pm0, __shfl_xor_sync(0xffffffffu, pm0, o));
            pm1 = fmaxf(pm1, __shfl_xor_sync(0xffffffffu, pm1, o));
        }
        float mn0 = fmaxf(m0, pm0), mn1 = fmaxf(m1, pm1);
        float a0 = __expf(m0 - mn0), a1 = __expf(m1 - mn1);
        m0 = mn0; m1 = mn1;

        float rs0 = 0.f, rs1 = 0.f;
        const int prow0 = wid * 16 + g, prow1 = prow0 + 8;
#pragma unroll
        for (int ni = 0; ni < 8; ni++) {
            float p0 = __expf(sa[ni][0] - mn0);
            float p1 = __expf(sa[ni][1] - mn0);
            float p2 = __expf(sa[ni][2] - mn1);
            float p3 = __expf(sa[ni][3] - mn1);
            rs0 += p0 + p1; rs1 += p2 + p3;
            uint32_t hp, lp;
            split2(p0, p1, hp, lp);
            *(uint32_t*)(asmem + 49152 + (prow0 << 7)
                         + ((ni ^ (prow0 & 7)) << 4) + t * 4) = hp;
            *(uint32_t*)(asmem + 57344 + (prow0 << 7)
                         + ((ni ^ (prow0 & 7)) << 4) + t * 4) = lp;
            split2(p2, p3, hp, lp);
            *(uint32_t*)(asmem + 49152 + (prow1 << 7)
                         + ((ni ^ (prow1 & 7)) << 4) + t * 4) = hp;
            *(uint32_t*)(asmem + 57344 + (prow1 << 7)
                         + ((ni ^ (prow1 & 7)) << 4) + t * 4) = lp;
        }
#pragma unroll
        for (int o = 1; o < 4; o <<= 1) {
            rs0 += __shfl_xor_sync(0xffffffffu, rs0, o);
            rs1 += __shfl_xor_sync(0xffffffffu, rs1, o);
        }
        l0 = l0 * a0 + rs0;
        l1 = l1 * a1 + rs1;
#pragma unroll
        for (int ni = 0; ni < 8; ni++) {
            O[ni][0] *= a0; O[ni][1] *= a0;
            O[ni][2] *= a1; O[ni][3] *= a1;
        }
        __syncwarp();

        {
            int arow = wid * 16 + (lane & 15);
            int akh2 = lane >> 4;
            int vrow = (lane & 7) + (((lane >> 3) & 1) << 3);
            int vch  = lane >> 4;
#pragma unroll
            for (int ks = 0; ks < 4; ks++) {
                uint32_t ao = swz8(arow, ks * 2 + akh2);
                uint32_t ph_[4], pl_[4];
                ldsm4(ph_, S + 49152 + ao);
                ldsm4(pl_, S + 57344 + ao);
#pragma unroll
                for (int nip = 0; nip < 4; nip++) {
                    uint32_t vo = swz8(ks * 16 + vrow, nip * 2 + vch);
                    uint32_t vh_[4], vl_[4];
                    ldsm4t(vh_, S + 32768 + vo);
                    ldsm4t(vl_, S + 40960 + vo);
                    mma16816(O[2 * nip],     ph_, vh_[0], vh_[1]);
                    mma16816(O[2 * nip + 1], ph_, vh_[2], vh_[3]);
                    mma16816(O[2 * nip],     ph_, vl_[0], vl_[1]);
                    mma16816(O[2 * nip + 1], ph_, vl_[2], vl_[3]);
                    mma16816(O[2 * nip],     pl_, vh_[0], vh_[1]);
                    mma16816(O[2 * nip + 1], pl_, vh_[2], vh_[3]);
                }
            }
        }
    }

    float inv0 = 1.0f / l0, inv1 = 1.0f / l1;
    const size_t gr0 = ((size_t)b * TT + row0a) * CC + h * 64;
    const size_t gr1 = ((size_t)b * TT + row1a) * CC + h * 64;
#pragma unroll
    for (int ni = 0; ni < 8; ni++) {
        int col = ni * 8 + t * 2;
        uint32_t hp, lp;
        split2(O[ni][0] * inv0, O[ni][1] * inv0, hp, lp);
        *(uint32_t*)(outh + gr0 + col) = hp;
        *(uint32_t*)(outl + gr0 + col) = lp;
        split2(O[ni][2] * inv1, O[ni][3] * inv1, hp, lp);
        *(uint32_t*)(outh + gr1 + col) = hp;
        *(uint32_t*)(outl + gr1 + col) = lp;
    }
}

// ---------------------------------------------------------------------------
// Fused split-K reduce + bias + LayerNorm + residual
// ---------------------------------------------------------------------------
__global__ void __launch_bounds__(256) ln_res2_kernel(
    const float* __restrict__ p, const float* __restrict__ bias,
    const float* __restrict__ g, const float* __restrict__ be,
    float* __restrict__ h,
    __nv_bfloat16* __restrict__ hh, __nv_bfloat16* __restrict__ hl)
{
    __shared__ float red1[8];
    __shared__ float red2[8];
    const int row = blockIdx.x;
    const int tid = threadIdx.x;
    const float* p0 = p + (size_t)row * CC;
    const float* p1 = p + (size_t)BT * CC + (size_t)row * CC;

    float v0 = p0[tid]       + p1[tid]       + bias[tid];
    float v1 = p0[tid + 256] + p1[tid + 256] + bias[tid + 256];
    float v2 = p0[tid + 512] + p1[tid + 512] + bias[tid + 512];
    float s = v0 + v1 + v2;
#pragma unroll
    for (int o = 16; o; o >>= 1) s += __shfl_xor_sync(0xffffffffu, s, o);
    if ((tid & 31) == 0) red1[tid >> 5] = s;
    __syncthreads();
    float tot = 0.f;
#pragma unroll
    for (int i = 0; i < 8; i++) tot += red1[i];
    float mu = tot * (1.0f / 768.0f);

    float d0 = v0 - mu, d1 = v1 - mu, d2 = v2 - mu;
    float q = d0 * d0 + d1 * d1 + d2 * d2;
#pragma unroll
    for (int o = 16; o; o >>= 1) q += __shfl_xor_sync(0xffffffffu, q, o);
    if ((tid & 31) == 0) red2[tid >> 5] = q;
    __syncthreads();
    float qt = 0.f;
#pragma unroll
    for (int i = 0; i < 8; i++) qt += red2[i];
    float rstd = rsqrtf(qt * (1.0f / 768.0f) + 1e-5f);

    float* hr = h + (size_t)row * CC;
    size_t ob = (size_t)row * CC;
#pragma unroll
    for (int pI = 0; pI < 3; pI++) {
        int c = tid + pI * 256;
        float dd = (pI == 0) ? d0 : (pI == 1) ? d1 : d2;
        float nv = hr[c] + dd * rstd * g[c] + be[c];
        hr[c] = nv;
        __nv_bfloat16 hb = __float2bfloat16_rn(nv);
        hh[ob + c] = hb;
        hl[ob + c] = __float2bfloat16_rn(nv - __bfloat162float(hb));
    }
}

// ---------------------------------------------------------------------------
// Launch
// ---------------------------------------------------------------------------
extern "C" void kernel_launch(void* const* d_in, const int* in_sizes, int n_in,
                              void* d_out, int out_size)
{
    const int*   x     = (const int*)  d_in[0];
    const float* embed = (const float*)d_in[1];
    const float* pos   = (const float*)d_in[2];
    const float* Wqkv  = (const float*)d_in[3];
    const float* bqkv  = (const float*)d_in[4];
    const float* W1a   = (const float*)d_in[5];
    const float* b1a   = (const float*)d_in[6];
    const float* W2a   = (const float*)d_in[7];
    const float* b2a   = (const float*)d_in[8];
    const float* g1    = (const float*)d_in[9];
    const float* beta1 = (const float*)d_in[10];
    const float* W1b   = (const float*)d_in[11];
    const float* b1b   = (const float*)d_in[12];
    const float* W2b   = (const float*)d_in[13];
    const float* b2b   = (const float*)d_in[14];
    const float* g2    = (const float*)d_in[15];
    const float* beta2 = (const float*)d_in[16];
    const float* lmW   = (const float*)d_in[17];
    const float* lmb   = (const float*)d_in[18];
    float* out = (float*)d_out;

    float *h, *part;
    __nv_bfloat16 *hh, *hl, *qvh, *qvl, *ath, *atl, *mih, *mil;
    cudaGetSymbolAddress((void**)&h,    g_h);
    cudaGetSymbolAddress((void**)&part, g_part);
    cudaGetSymbolAddress((void**)&hh,   g_hh);
    cudaGetSymbolAddress((void**)&hl,   g_hl);
    cudaGetSymbolAddress((void**)&qvh,  g_qvh);
    cudaGetSymbolAddress((void**)&qvl,  g_qvl);
    cudaGetSymbolAddress((void**)&ath,  g_ath);
    cudaGetSymbolAddress((void**)&atl,  g_atl);
    cudaGetSymbolAddress((void**)&mih,  g_mih);
    cudaGetSymbolAddress((void**)&mil,  g_mil);

    __nv_bfloat16 *wqh, *wql, *w1ah, *w1al, *w2ah, *w2al,
                  *w1bh, *w1bl, *w2bh, *w2bl, *lmh, *lml;
    cudaGetSymbolAddress((void**)&wqh,  g_wqkv_h);
    cudaGetSymbolAddress((void**)&wql,  g_wqkv_l);
    cudaGetSymbolAddress((void**)&w1ah, g_w1a_h);
    cudaGetSymbolAddress((void**)&w1al, g_w1a_l);
    cudaGetSymbolAddress((void**)&w2ah, g_w2a_h);
    cudaGetSymbolAddress((void**)&w2al, g_w2a_l);
    cudaGetSymbolAddress((void**)&w1bh, g_w1b_h);
    cudaGetSymbolAddress((void**)&w1bl, g_w1b_l);
    cudaGetSymbolAddress((void**)&w2bh, g_w2b_h);
    cudaGetSymbolAddress((void**)&w2bl, g_w2b_l);
    cudaGetSymbolAddress((void**)&lmh,  g_lm_h);
    cudaGetSymbolAddress((void**)&lml,  g_lm_l);

    cudaFuncSetAttribute(hgemm_s4_kernel<0,0,1>,
        cudaFuncAttributeMaxDynamicSharedMemorySize, SMQ4);
    cudaFuncSetAttribute(hgemm_s4_kernel<1,0,1>,
        cudaFuncAttributeMaxDynamicSharedMemorySize, SMQ4);
    cudaFuncSetAttribute(hgemm_s4_kernel<0,1,0>,
        cudaFuncAttributeMaxDynamicSharedMemorySize, SMQ4);
    cudaFuncSetAttribute(hgemm_s4_pk_kernel,
        cudaFuncAttributeMaxDynamicSharedMemorySize, SMQ4);
    cudaFuncSetAttribute(attn_hmma_kernel,
        cudaFuncAttributeMaxDynamicSharedMemorySize, ASMEM);

    const dim3 cb(32, 8);
    // launch order keeps ncu capture (idx 3) on the first qkv GEMM
    convert_w_kernel<<<dim3(3 * CC / 32, CC / 32, LNUM), cb>>>(
        Wqkv, wqh, wql, CC, 3 * CC);                              // 0
    convert_w2_kernel<<<dim3(FFF / 32, CC / 32, 2 * LNUM), cb>>>(
        W1a, W1b, w1ah, w1al, w1bh, w1bl, CC, FFF);               // 1
    embed_kernel<<<BT, 192>>>(x, embed, pos, h, hh, hl);          // 2

    const dim3 grid_qkv (3 * CC / 64, BT / 128);
    const dim3 grid_ffn1(FFF / 64,    BT / 128);
    const dim3 grid_ffn2(CC / 64,     BT / 128, 2);   // split-K 2
    const dim3 grid_lm  (VV / 64,     BT / 128);
    const dim3 grid_attn(TT / 64, BB * HH);

    for (int l = 0; l < LNUM; l++) {
        hgemm_s4_kernel<0,0,1><<<grid_qkv, 128, SMQ4>>>(          // 3 (l=0)
            hh, hl, wqh + (size_t)l * 3 * CC * CC, wql + (size_t)l * 3 * CC * CC,
            bqkv + (size_t)l * 3 * CC, nullptr, qvh, qvl, 3 * CC, CC);
        attn_hmma_kernel<<<grid_attn, 128, ASMEM>>>(qvh, qvl, ath, atl);
        if (l == 0) {
            convert_w2_kernel<<<dim3(CC / 32, FFF / 32, 2 * LNUM), cb>>>(
                W2a, W2b, w2ah, w2al, w2bh, w2bl, FFF, CC);
        }
        hgemm_s4_kernel<1,0,1><<<grid_ffn1, 128, SMQ4>>>(
            ath, atl, w1ah + (size_t)l * CC * FFF, w1al + (size_t)l * CC * FFF,
            b1a + (size_t)l * FFF, nullptr, mih, mil, FFF, CC);
        hgemm_s4_pk_kernel<<<grid_ffn2, 128, SMQ4>>>(
            mih, mil, w2ah + (size_t)l * CC * FFF, w2al + (size_t)l * CC * FFF,
            part, BT, CC, FFF);
        ln_res2_kernel<<<BT, 256>>>(part, b2a + (size_t)l * CC,
                                    g1 + (size_t)l * CC,
                                    beta1 + (size_t)l * CC, h, hh, hl);
        hgemm_s4_kernel<1,0,1><<<grid_ffn1, 128, SMQ4>>>(
            hh, hl, w1bh + (size_t)l * CC * FFF, w1bl + (size_t)l * CC * FFF,
            b1b + (size_t)l * FFF, nullptr, mih, mil, FFF, CC);
        hgemm_s4_pk_kernel<<<grid_ffn2, 128, SMQ4>>>(
            mih, mil, w2bh + (size_t)l * CC * FFF, w2bl + (size_t)l * CC * FFF,
            part, BT, CC, FFF);
        ln_res2_kernel<<<BT, 256>>>(part, b2b + (size_t)l * CC,
                                    g2 + (size_t)l * CC,
                                    beta2 + (size_t)l * CC, h, hh, hl);
    }

    convert_w_kernel<<<dim3(VV / 32, CC / 32, 1), cb>>>(lmW, lmh, lml, CC, VV);
    hgemm_s4_kernel<0,1,0><<<grid_lm, 128, SMQ4>>>(
        hh, hl, lmh, lml, lmb, out, nullptr, nullptr, VV, CC);
}

// round 13
// speedup vs baseline: 1.0467x; 1.0467x over previous
#include <cuda_runtime.h>
#include <cuda_bf16.h>
#include <math.h>
#include <stdint.h>

#define LNUM 8
#define BB   8
#define TT   1024
#define CC   768
#define HH   12
#define DD   64
#define VV   1024
#define FFF  3072
#define BT   (BB*TT)   // 8192

// ---------------------------------------------------------------------------
// Scratch activations
// ---------------------------------------------------------------------------
__device__ float g_part[2 * BT * CC];          // FFN2 split-K partials
__device__ float g_h  [BT * CC];
__device__ __nv_bfloat16 g_hh [BT * CC];
__device__ __nv_bfloat16 g_hl [BT * CC];
__device__ __nv_bfloat16 g_qvh[BT * 3 * CC];
__device__ __nv_bfloat16 g_qvl[BT * 3 * CC];
__device__ __nv_bfloat16 g_ath[BT * CC];
__device__ __nv_bfloat16 g_atl[BT * CC];
__device__ __nv_bfloat16 g_mih[BT * FFF];
__device__ __nv_bfloat16 g_mil[BT * FFF];

// ---------------------------------------------------------------------------
// Pre-converted weights: transposed [N][K], bf16 hi/lo split
// ---------------------------------------------------------------------------
__device__ __nv_bfloat16 g_wqkv_h[LNUM * 3 * CC * CC];
__device__ __nv_bfloat16 g_wqkv_l[LNUM * 3 * CC * CC];
__device__ __nv_bfloat16 g_w1a_h [LNUM * CC * FFF];
__device__ __nv_bfloat16 g_w1a_l [LNUM * CC * FFF];
__device__ __nv_bfloat16 g_w2a_h [LNUM * CC * FFF];
__device__ __nv_bfloat16 g_w2a_l [LNUM * CC * FFF];
__device__ __nv_bfloat16 g_w1b_h [LNUM * CC * FFF];
__device__ __nv_bfloat16 g_w1b_l [LNUM * CC * FFF];
__device__ __nv_bfloat16 g_w2b_h [LNUM * CC * FFF];
__device__ __nv_bfloat16 g_w2b_l [LNUM * CC * FFF];
__device__ __nv_bfloat16 g_lm_h  [VV * CC];
__device__ __nv_bfloat16 g_lm_l  [VV * CC];

// ---------------------------------------------------------------------------
// Helpers
// ---------------------------------------------------------------------------
__device__ __forceinline__ float gelu_f(float x) {
    return 0.5f * x * (1.0f + erff(x * 0.70710678118654752f));
}

__device__ __forceinline__ uint32_t smem_u32(const void* p) {
    uint32_t a;
    asm("{ .reg .u64 t; cvta.to.shared.u64 t, %1; cvt.u32.u64 %0, t; }"
        : "=r"(a) : "l"(p));
    return a;
}

__device__ __forceinline__ void cpa16(uint32_t s, const void* g) {
    asm volatile("cp.async.cg.shared.global [%0], [%1], 16;"
                 :: "r"(s), "l"(g));
}
#define CP_COMMIT() asm volatile("cp.async.commit_group;" ::: "memory")
#define CP_WAIT1()  asm volatile("cp.async.wait_group 1;" ::: "memory")
#define CP_WAIT0()  asm volatile("cp.async.wait_group 0;" ::: "memory")

__device__ __forceinline__ void ldsm4(uint32_t* r, uint32_t a) {
    asm volatile("ldmatrix.sync.aligned.m8n8.x4.shared.b16 {%0,%1,%2,%3}, [%4];"
        : "=r"(r[0]), "=r"(r[1]), "=r"(r[2]), "=r"(r[3]) : "r"(a));
}
__device__ __forceinline__ void ldsm4t(uint32_t* r, uint32_t a) {
    asm volatile("ldmatrix.sync.aligned.m8n8.x4.trans.shared.b16 {%0,%1,%2,%3}, [%4];"
        : "=r"(r[0]), "=r"(r[1]), "=r"(r[2]), "=r"(r[3]) : "r"(a));
}

__device__ __forceinline__ void mma16816(float* c, const uint32_t* a,
                                         uint32_t b0, uint32_t b1) {
    asm volatile(
        "mma.sync.aligned.m16n8k16.row.col.f32.bf16.bf16.f32 "
        "{%0,%1,%2,%3}, {%4,%5,%6,%7}, {%8,%9}, {%0,%1,%2,%3};"
        : "+f"(c[0]), "+f"(c[1]), "+f"(c[2]), "+f"(c[3])
        : "r"(a[0]), "r"(a[1]), "r"(a[2]), "r"(a[3]), "r"(b0), "r"(b1));
}

__device__ __forceinline__ uint32_t pack_bf2(float a, float b) {
    __nv_bfloat162 p = __floats2bfloat162_rn(a, b);
    return *reinterpret_cast<uint32_t*>(&p);
}
__device__ __forceinline__ void split2(float v0, float v1,
                                       uint32_t& hp, uint32_t& lp) {
    __nv_bfloat16 h0 = __float2bfloat16_rn(v0);
    __nv_bfloat16 h1 = __float2bfloat16_rn(v1);
    float l0 = v0 - __bfloat162float(h0);
    float l1 = v1 - __bfloat162float(h1);
    __nv_bfloat162 hh = __halves2bfloat162(h0, h1);
    hp = *reinterpret_cast<uint32_t*>(&hh);
    lp = pack_bf2(l0, l1);
}

// GEMM smem swizzle: 64B rows, 4 chunks of 16B, chunk ^= (row>>1)&3
__device__ __forceinline__ uint32_t swz(int row, int c) {
    return (uint32_t)((row << 6) + (((c ^ ((row >> 1) & 3)) << 4)));
}
// Attention smem swizzle: 128B rows, 8 chunks of 16B, chunk ^= row&7
__device__ __forceinline__ uint32_t swz8(int row, int c) {
    return (uint32_t)((row << 7) + (((c ^ (row & 7)) << 4)));
}

// ---------------------------------------------------------------------------
// Weight pre-convert
// ---------------------------------------------------------------------------
__device__ __forceinline__ void convert_body(
    const float* __restrict__ Wl, __nv_bfloat16* __restrict__ hl,
    __nv_bfloat16* __restrict__ ll, int K, int N)
{
    __shared__ float t[32][33];
    const int kb = blockIdx.y << 5, nb = blockIdx.x << 5;
    const int tx = threadIdx.x, ty = threadIdx.y;
#pragma unroll
    for (int i = 0; i < 32; i += 8)
        t[ty + i][tx] = Wl[(size_t)(kb + ty + i) * N + nb + tx];
    __syncthreads();
#pragma unroll
    for (int i = 0; i < 32; i += 8) {
        float v = t[tx][ty + i];
        __nv_bfloat16 h = __float2bfloat16_rn(v);
        __nv_bfloat16 l = __float2bfloat16_rn(v - __bfloat162float(h));
        size_t o = (size_t)(nb + ty + i) * K + kb + tx;
        hl[o] = h; ll[o] = l;
    }
}

__global__ void __launch_bounds__(256) convert_w_kernel(
    const float* __restrict__ W, __nv_bfloat16* __restrict__ hi,
    __nv_bfloat16* __restrict__ lo, int K, int N)
{
    const size_t loff = (size_t)blockIdx.z * K * N;
    convert_body(W + loff, hi + loff, lo + loff, K, N);
}

__global__ void __launch_bounds__(256) convert_w2_kernel(
    const float* __restrict__ Wa, const float* __restrict__ Wb,
    __nv_bfloat16* __restrict__ hia, __nv_bfloat16* __restrict__ loa,
    __nv_bfloat16* __restrict__ hib, __nv_bfloat16* __restrict__ lob,
    int K, int N)
{
    int z = blockIdx.z;
    const float* W; __nv_bfloat16 *hi, *lo;
    if (z < LNUM) {
        size_t o = (size_t)z * K * N;
        W = Wa + o; hi = hia + o; lo = loa + o;
    } else {
        size_t o = (size_t)(z - LNUM) * K * N;
        W = Wb + o; hi = hib + o; lo = lob + o;
    }
    convert_body(W, hi, lo, K, N);
}

// ---------------------------------------------------------------------------
// HMMA GEMM S4 (R11 config): 128x64 CTA tile, 128 threads (4 warps in M),
// 2-stage pipeline, 48KB smem -> 4 CTAs/SM.
// ---------------------------------------------------------------------------
#define TA4 (128 * 64)                  // 8192 B
#define TB4 (64 * 64)                   // 4096 B
#define STG4 (2 * TA4 + 2 * TB4)        // 24576 B
#define SMQ4 (2 * STG4)                 // 49152 B

template<int EPI, int WF32, int WHL>
__global__ void __launch_bounds__(128, 4) hgemm_s4_kernel(
    const __nv_bfloat16* __restrict__ Ah, const __nv_bfloat16* __restrict__ Al,
    const __nv_bfloat16* __restrict__ Bh, const __nv_bfloat16* __restrict__ Bl,
    const float* __restrict__ bias, float* __restrict__ C,
    __nv_bfloat16* __restrict__ Ch, __nv_bfloat16* __restrict__ Cl,
    int N, int K)
{
    extern __shared__ __align__(128) char smem[];
    const int tid  = threadIdx.x;
    const int lane = tid & 31;
    const int wid  = tid >> 5;
    const int g    = lane >> 2, t = lane & 3;
    const int bm   = blockIdx.y << 7, bn = blockIdx.x << 6;
    const uint32_t sbase = smem_u32(smem);

    const __nv_bfloat16* gpA[2] = { Ah + (size_t)bm * K, Al + (size_t)bm * K };
    const __nv_bfloat16* gpB[2] = { Bh + (size_t)bn * K, Bl + (size_t)bn * K };

    float acc[2][8][4];
#pragma unroll
    for (int mi = 0; mi < 2; mi++)
#pragma unroll
        for (int ni = 0; ni < 8; ni++)
#pragma unroll
            for (int r = 0; r < 4; r++) acc[mi][ni][r] = 0.f;

    const int nk = K >> 5;
    const int srow = tid >> 2, schk = tid & 3;

    auto stage = [&](int kt, int buf) {
        uint32_t s0 = sbase + buf * STG4;
        const int kc = kt * 32 + schk * 8;
#pragma unroll
        for (int m = 0; m < 2; m++) {
#pragma unroll
            for (int i = 0; i < 4; i++) {
                int row = srow + i * 32;
                cpa16(s0 + m * TA4 + swz(row, schk),
                      gpA[m] + (size_t)row * K + kc);
            }
#pragma unroll
            for (int i = 0; i < 2; i++) {
                int row = srow + i * 32;
                cpa16(s0 + 2 * TA4 + m * TB4 + swz(row, schk),
                      gpB[m] + (size_t)row * K + kc);
            }
        }
        CP_COMMIT();
    };

    stage(0, 0);
    stage(1, 1);

    const int arow0 = wid * 32 + (lane & 15);
    const int akh   = lane >> 4;
    const int brow0 = (lane & 7) + ((lane >> 4) << 3);
    const int bkh   = (lane >> 3) & 1;

    for (int kt = 0; kt < nk; kt++) {
        CP_WAIT1();
        __syncthreads();

        const uint32_t st  = sbase + (kt & 1) * STG4;
        const uint32_t Ahp = st, Alp = st + TA4;
        const uint32_t Bhp = st + 2 * TA4, Blp = st + 2 * TA4 + TB4;

#pragma unroll
        for (int ks = 0; ks < 2; ks++) {
            uint32_t ah[2][4], al[2][4];
#pragma unroll
            for (int mi = 0; mi < 2; mi++) {
                int row = arow0 + mi * 16;
                uint32_t ao = swz(row, ks * 2 + akh);
                ldsm4(ah[mi], Ahp + ao);
                ldsm4(al[mi], Alp + ao);
            }
#pragma unroll
            for (int nip = 0; nip < 4; nip++) {
                int row = brow0 + nip * 16;
                uint32_t bo = swz(row, ks * 2 + bkh);
                uint32_t bh[4], bl[4];
                ldsm4(bh, Bhp + bo);
                ldsm4(bl, Blp + bo);
#pragma unroll
                for (int mi = 0; mi < 2; mi++) {
                    mma16816(acc[mi][2 * nip],     ah[mi], bh[0], bh[1]);
                    mma16816(acc[mi][2 * nip + 1], ah[mi], bh[2], bh[3]);
                }
#pragma unroll
                for (int mi = 0; mi < 2; mi++) {
                    mma16816(acc[mi][2 * nip],     ah[mi], bl[0], bl[1]);
                    mma16816(acc[mi][2 * nip + 1], ah[mi], bl[2], bl[3]);
                }
#pragma unroll
                for (int mi = 0; mi < 2; mi++) {
                    mma16816(acc[mi][2 * nip],     al[mi], bh[0], bh[1]);
                    mma16816(acc[mi][2 * nip + 1], al[mi], bh[2], bh[3]);
                }
            }
        }

        __syncthreads();
        if (kt + 2 < nk) stage(kt + 2, kt & 1); else CP_COMMIT();
    }

#pragma unroll
    for (int ni = 0; ni < 8; ni++) {
        int col = bn + ni * 8 + t * 2;
        float b0 = bias[col], b1 = bias[col + 1];
#pragma unroll
        for (int mi = 0; mi < 2; mi++) {
            int r0 = bm + wid * 32 + mi * 16 + g;
            float v0 = acc[mi][ni][0] + b0;
            float v1 = acc[mi][ni][1] + b1;
            float v2 = acc[mi][ni][2] + b0;
            float v3 = acc[mi][ni][3] + b1;
            if (EPI == 1) {
                v0 = gelu_f(v0); v1 = gelu_f(v1);
                v2 = gelu_f(v2); v3 = gelu_f(v3);
            }
            size_t o0 = (size_t)r0 * N + col;
            size_t o1 = (size_t)(r0 + 8) * N + col;
            if (WF32) {
                *(float2*)(C + o0) = make_float2(v0, v1);
                *(float2*)(C + o1) = make_float2(v2, v3);
            }
            if (WHL) {
                uint32_t hp, lp;
                split2(v0, v1, hp, lp);
                *(uint32_t*)(Ch + o0) = hp;
                *(uint32_t*)(Cl + o0) = lp;
                split2(v2, v3, hp, lp);
                *(uint32_t*)(Ch + o1) = hp;
                *(uint32_t*)(Cl + o1) = lp;
            }
        }
    }
}

// ---------------------------------------------------------------------------
// HMMA GEMM S4 split-K2 partial (FFN2, R11 config)
// ---------------------------------------------------------------------------
__global__ void __launch_bounds__(128, 4) hgemm_s4_pk_kernel(
    const __nv_bfloat16* __restrict__ Ah, const __nv_bfloat16* __restrict__ Al,
    const __nv_bfloat16* __restrict__ Bh, const __nv_bfloat16* __restrict__ Bl,
    float* __restrict__ P, int M, int N, int K)
{
    extern __shared__ __align__(128) char smem[];
    const int tid  = threadIdx.x;
    const int lane = tid & 31;
    const int wid  = tid >> 5;
    const int g    = lane >> 2, t = lane & 3;
    const int bm   = blockIdx.y << 7, bn = blockIdx.x << 6;
    const int z    = blockIdx.z;
    const int Kh   = K >> 1;
    const int kc0  = z * Kh;
    const uint32_t sbase = smem_u32(smem);

    const __nv_bfloat16* gpA[2] = { Ah + (size_t)bm * K + kc0,
                                    Al + (size_t)bm * K + kc0 };
    const __nv_bfloat16* gpB[2] = { Bh + (size_t)bn * K + kc0,
                                    Bl + (size_t)bn * K + kc0 };

    float acc[2][8][4];
#pragma unroll
    for (int mi = 0; mi < 2; mi++)
#pragma unroll
        for (int ni = 0; ni < 8; ni++)
#pragma unroll
            for (int r = 0; r < 4; r++) acc[mi][ni][r] = 0.f;

    const int nk = Kh >> 5;
    const int srow = tid >> 2, schk = tid & 3;

    auto stage = [&](int kt, int buf) {
        uint32_t s0 = sbase + buf * STG4;
        const int kc = kt * 32 + schk * 8;
#pragma unroll
        for (int m = 0; m < 2; m++) {
#pragma unroll
            for (int i = 0; i < 4; i++) {
                int row = srow + i * 32;
                cpa16(s0 + m * TA4 + swz(row, schk),
                      gpA[m] + (size_t)row * K + kc);
            }
#pragma unroll
            for (int i = 0; i < 2; i++) {
                int row = srow + i * 32;
                cpa16(s0 + 2 * TA4 + m * TB4 + swz(row, schk),
                      gpB[m] + (size_t)row * K + kc);
            }
        }
        CP_COMMIT();
    };

    stage(0, 0);
    stage(1, 1);

    const int arow0 = wid * 32 + (lane & 15);
    const int akh   = lane >> 4;
    const int brow0 = (lane & 7) + ((lane >> 4) << 3);
    const int bkh   = (lane >> 3) & 1;

    for (int kt = 0; kt < nk; kt++) {
        CP_WAIT1();
        __syncthreads();

        const uint32_t st  = sbase + (kt & 1) * STG4;
        const uint32_t Ahp = st, Alp = st + TA4;
        const uint32_t Bhp = st + 2 * TA4, Blp = st + 2 * TA4 + TB4;

#pragma unroll
        for (int ks = 0; ks < 2; ks++) {
            uint32_t ah[2][4], al[2][4];
#pragma unroll
            for (int mi = 0; mi < 2; mi++) {
                int row = arow0 + mi * 16;
                uint32_t ao = swz(row, ks * 2 + akh);
                ldsm4(ah[mi], Ahp + ao);
                ldsm4(al[mi], Alp + ao);
            }
#pragma unroll
            for (int nip = 0; nip < 4; nip++) {
                int row = brow0 + nip * 16;
                uint32_t bo = swz(row, ks * 2 + bkh);
                uint32_t bh[4], bl[4];
                ldsm4(bh, Bhp + bo);
                ldsm4(bl, Blp + bo);
#pragma unroll
                for (int mi = 0; mi < 2; mi++) {
                    mma16816(acc[mi][2 * nip],     ah[mi], bh[0], bh[1]);
                    mma16816(acc[mi][2 * nip + 1], ah[mi], bh[2], bh[3]);
                }
#pragma unroll
                for (int mi = 0; mi < 2; mi++) {
                    mma16816(acc[mi][2 * nip],     ah[mi], bl[0], bl[1]);
                    mma16816(acc[mi][2 * nip + 1], ah[mi], bl[2], bl[3]);
                }
#pragma unroll
                for (int mi = 0; mi < 2; mi++) {
                    mma16816(acc[mi][2 * nip],     al[mi], bh[0], bh[1]);
                    mma16816(acc[mi][2 * nip + 1], al[mi], bh[2], bh[3]);
                }
            }
        }

        __syncthreads();
        if (kt + 2 < nk) stage(kt + 2, kt & 1); else CP_COMMIT();
    }

    float* Pz = P + (size_t)z * M * N;
#pragma unroll
    for (int ni = 0; ni < 8; ni++) {
        int col = bn + ni * 8 + t * 2;
#pragma unroll
        for (int mi = 0; mi < 2; mi++) {
            int r0 = bm + wid * 32 + mi * 16 + g;
            *(float2*)(Pz + (size_t)r0 * N + col) =
                make_float2(acc[mi][ni][0], acc[mi][ni][1]);
            *(float2*)(Pz + (size_t)(r0 + 8) * N + col) =
                make_float2(acc[mi][ni][2], acc[mi][ni][3]);
        }
    }
}

// ---------------------------------------------------------------------------
// Embedding
// ---------------------------------------------------------------------------
__global__ void __launch_bounds__(192) embed_kernel(
    const int* __restrict__ x, const float* __restrict__ emb,
    const float* __restrict__ pos, float* __restrict__ h,
    __nv_bfloat16* __restrict__ hh, __nv_bfloat16* __restrict__ hl)
{
    const int bt  = blockIdx.x;
    const int tok = x[bt];
    const int t   = bt & (TT - 1);
    const float4* e4 = (const float4*)(emb + (size_t)tok * CC);
    const float4* p4 = (const float4*)(pos + (size_t)t   * CC);
    const int i = threadIdx.x;
    float4 a = e4[i], b = p4[i];
    float4 s = make_float4(a.x + b.x, a.y + b.y, a.z + b.z, a.w + b.w);
    ((float4*)(h + (size_t)bt * CC))[i] = s;
    size_t o = (size_t)bt * CC + i * 4;
    uint32_t hp, lp;
    split2(s.x, s.y, hp, lp);
    *(uint32_t*)(hh + o) = hp;     *(uint32_t*)(hl + o) = lp;
    split2(s.z, s.w, hp, lp);
    *(uint32_t*)(hh + o + 2) = hp; *(uint32_t*)(hl + o + 2) = lp;
}

// ---------------------------------------------------------------------------
// HMMA flash attention: 64x64 tiles, 4 warps, 64KB smem.
// K/V/Q staging via cp.async (fire-and-forget, no LDG->reg->STS round trip).
// ---------------------------------------------------------------------------
#define ASMEM (8 * 8192)

__global__ void __launch_bounds__(128) attn_hmma_kernel(
    const __nv_bfloat16* __restrict__ qkvh,
    const __nv_bfloat16* __restrict__ qkvl,
    __nv_bfloat16* __restrict__ outh, __nv_bfloat16* __restrict__ outl)
{
    extern __shared__ __align__(128) char asmem[];
    const int tid  = threadIdx.x;
    const int lane = tid & 31, wid = tid >> 5;
    const int g    = lane >> 2, t = lane & 3;
    const int qtile = blockIdx.x, bh = blockIdx.y;
    const int b = bh / HH, h = bh % HH;
    const int qb = qtile << 6;
    const uint32_t S = smem_u32(asmem);
    const size_t bbase = (size_t)b * TT * 3 * CC;

    auto stage64 = [&](uint32_t off, const __nv_bfloat16* src,
                       int tok0, int coff) {
#pragma unroll
        for (int i = 0; i < 4; i++) {
            int idx = tid + (i << 7);
            int row = idx >> 3, chk = idx & 7;
            cpa16(S + off + swz8(row, chk),
                  src + bbase + (size_t)(tok0 + row) * (3 * CC)
                      + coff + chk * 8);
        }
    };

    stage64(0,    qkvh, qb, CC + h * 64);
    stage64(8192, qkvl, qb, CC + h * 64);
    CP_COMMIT();
    CP_WAIT0();
    __syncthreads();

    uint32_t qh[4][4], ql[4][4];
    {
        int row = wid * 16 + (lane & 15);
        int kh  = lane >> 4;
#pragma unroll
        for (int ks = 0; ks < 4; ks++) {
            uint32_t ao = swz8(row, ks * 2 + kh);
            ldsm4(qh[ks], S + 0 + ao);
            ldsm4(ql[ks], S + 8192 + ao);
        }
    }

    float O[8][4];
#pragma unroll
    for (int ni = 0; ni < 8; ni++)
#pragma unroll
        for (int r = 0; r < 4; r++) O[ni][r] = 0.f;
    float m0 = -1e30f, m1 = -1e30f, l0 = 0.f, l1 = 0.f;

    const int row0a = qb + wid * 16 + g;
    const int row1a = row0a + 8;

    for (int kt = 0; kt <= qtile; kt++) {
        const int kb = kt << 6;
        __syncthreads();
        stage64(16384, qkvh, kb, h * 64);
        stage64(24576, qkvl, kb, h * 64);
        stage64(32768, qkvh, kb, 2 * CC + h * 64);
        stage64(40960, qkvl, kb, 2 * CC + h * 64);
        CP_COMMIT();
        CP_WAIT0();
        __syncthreads();

        float sa[8][4];
#pragma unroll
        for (int ni = 0; ni < 8; ni++)
#pragma unroll
            for (int r = 0; r < 4; r++) sa[ni][r] = 0.f;
        {
            int brow = (lane & 7) + ((lane >> 4) << 3);
            int bkh  = (lane >> 3) & 1;
#pragma unroll
            for (int ks = 0; ks < 4; ks++) {
#pragma unroll
                for (int nip = 0; nip < 4; nip++) {
                    uint32_t bo = swz8(nip * 16 + brow, ks * 2 + bkh);
                    uint32_t kh_[4], kl_[4];
                    ldsm4(kh_, S + 16384 + bo);
                    ldsm4(kl_, S + 24576 + bo);
                    mma16816(sa[2 * nip],     qh[ks], kh_[0], kh_[1]);
                    mma16816(sa[2 * nip + 1], qh[ks], kh_[2], kh_[3]);
                    mma16816(sa[2 * nip],     qh[ks], kl_[0], kl_[1]);
                    mma16816(sa[2 * nip + 1], qh[ks], kl_[2], kl_[3]);
                    mma16816(sa[2 * nip],     ql[ks], kh_[0], kh_[1]);
                    mma16816(sa[2 * nip + 1], ql[ks], kh_[2], kh_[3]);
                }
            }
        }

        const bool diag = (kt == qtile);
#pragma unroll
        for (int ni = 0; ni < 8; ni++) {
            int c0 = kb + ni * 8 + t * 2, c1 = c0 + 1;
            sa[ni][0] *= 0.125f; sa[ni][1] *= 0.125f;
            sa[ni][2] *= 0.125f; sa[ni][3] *= 0.125f;
            if (diag) {
                if (c0 > row0a) sa[ni][0] = -1e30f;
                if (c1 > row0a) sa[ni][1] = -1e30f;
                if (c0 > row1a) sa[ni][2] = -1e30f;
                if (c1 > row1a) sa[ni][3] = -1e30f;
            }
        }

        float pm0 = -1e30f, pm1 = -1e30f;
#pragma unroll
        for (int ni = 0; ni < 8; ni++) {
            pm0 = fmaxf(pm0, fmaxf(sa[ni][0], sa[ni][1]));
            pm1 = fmaxf(pm1, fmaxf(sa[ni][2], sa[ni][3]));
        }
#pragma unroll
        for (int o = 1; o < 4; o <<= 1) {
            pm0 = fmaxf(pm0, __shfl_xor_sync(0xffffffffu, pm0, o));
            pm1 = fmaxf(pm1, __shfl_xor_sync(0xffffffffu, pm1, o));
        }
        float mn0 = fmaxf(m0, pm0), mn1 = fmaxf(m1, pm1);
        float a0 = __expf(m0 - mn0), a1 = __expf(m1 - mn1);
        m0 = mn0; m1 = mn1;

        float rs0 = 0.f, rs1 = 0.f;
        const int prow0 = wid * 16 + g, prow1 = prow0 + 8;
#pragma unroll
        for (int ni = 0; ni < 8; ni++) {
            float p0 = __expf(sa[ni][0] - mn0);
            float p1 = __expf(sa[ni][1] - mn0);
            float p2 = __expf(sa[ni][2] - mn1);
            float p3 = __expf(sa[ni][3] - mn1);
            rs0 += p0 + p1; rs1 += p2 + p3;
            uint32_t hp, lp;
            split2(p0, p1, hp, lp);
            *(uint32_t*)(asmem + 49152 + (prow0 << 7)
                         + ((ni ^ (prow0 & 7)) << 4) + t * 4) = hp;
            *(uint32_t*)(asmem + 57344 + (prow0 << 7)
                         + ((ni ^ (prow0 & 7)) << 4) + t * 4) = lp;
            split2(p2, p3, hp, lp);
            *(uint32_t*)(asmem + 49152 + (prow1 << 7)
                         + ((ni ^ (prow1 & 7)) << 4) + t * 4) = hp;
            *(uint32_t*)(asmem + 57344 + (prow1 << 7)
                         + ((ni ^ (prow1 & 7)) << 4) + t * 4) = lp;
        }
#pragma unroll
        for (int o = 1; o < 4; o <<= 1) {
            rs0 += __shfl_xor_sync(0xffffffffu, rs0, o);
            rs1 += __shfl_xor_sync(0xffffffffu, rs1, o);
        }
        l0 = l0 * a0 + rs0;
        l1 = l1 * a1 + rs1;
#pragma unroll
        for (int ni = 0; ni < 8; ni++) {
            O[ni][0] *= a0; O[ni][1] *= a0;
            O[ni][2] *= a1; O[ni][3] *= a1;
        }
        __syncwarp();

        {
            int arow = wid * 16 + (lane & 15);
            int akh2 = lane >> 4;
            int vrow = (lane & 7) + (((lane >> 3) & 1) << 3);
            int vch  = lane >> 4;
#pragma unroll
            for (int ks = 0; ks < 4; ks++) {
                uint32_t ao = swz8(arow, ks * 2 + akh2);
                uint32_t ph_[4], pl_[4];
                ldsm4(ph_, S + 49152 + ao);
                ldsm4(pl_, S + 57344 + ao);
#pragma unroll
                for (int nip = 0; nip < 4; nip++) {
                    uint32_t vo = swz8(ks * 16 + vrow, nip * 2 + vch);
                    uint32_t vh_[4], vl_[4];
                    ldsm4t(vh_, S + 32768 + vo);
                    ldsm4t(vl_, S + 40960 + vo);
                    mma16816(O[2 * nip],     ph_, vh_[0], vh_[1]);
                    mma16816(O[2 * nip + 1], ph_, vh_[2], vh_[3]);
                    mma16816(O[2 * nip],     ph_, vl_[0], vl_[1]);
                    mma16816(O[2 * nip + 1], ph_, vl_[2], vl_[3]);
                    mma16816(O[2 * nip],     pl_, vh_[0], vh_[1]);
                    mma16816(O[2 * nip + 1], pl_, vh_[2], vh_[3]);
                }
            }
        }
    }

    float inv0 = 1.0f / l0, inv1 = 1.0f / l1;
    const size_t gr0 = ((size_t)b * TT + row0a) * CC + h * 64;
    const size_t gr1 = ((size_t)b * TT + row1a) * CC + h * 64;
#pragma unroll
    for (int ni = 0; ni < 8; ni++) {
        int col = ni * 8 + t * 2;
        uint32_t hp, lp;
        split2(O[ni][0] * inv0, O[ni][1] * inv0, hp, lp);
        *(uint32_t*)(outh + gr0 + col) = hp;
        *(uint32_t*)(outl + gr0 + col) = lp;
        split2(O[ni][2] * inv1, O[ni][3] * inv1, hp, lp);
        *(uint32_t*)(outh + gr1 + col) = hp;
        *(uint32_t*)(outl + gr1 + col) = lp;
    }
}

// ---------------------------------------------------------------------------
// Fused split-K reduce + bias + LayerNorm + residual
// ---------------------------------------------------------------------------
__global__ void __launch_bounds__(256) ln_res2_kernel(
    const float* __restrict__ p, const float* __restrict__ bias,
    const float* __restrict__ g, const float* __restrict__ be,
    float* __restrict__ h,
    __nv_bfloat16* __restrict__ hh, __nv_bfloat16* __restrict__ hl)
{
    __shared__ float red1[8];
    __shared__ float red2[8];
    const int row = blockIdx.x;
    const int tid = threadIdx.x;
    const float* p0 = p + (size_t)row * CC;
    const float* p1 = p + (size_t)BT * CC + (size_t)row * CC;

    float v0 = p0[tid]       + p1[tid]       + bias[tid];
    float v1 = p0[tid + 256] + p1[tid + 256] + bias[tid + 256];
    float v2 = p0[tid + 512] + p1[tid + 512] + bias[tid + 512];
    float s = v0 + v1 + v2;
#pragma unroll
    for (int o = 16; o; o >>= 1) s += __shfl_xor_sync(0xffffffffu, s, o);
    if ((tid & 31) == 0) red1[tid >> 5] = s;
    __syncthreads();
    float tot = 0.f;
#pragma unroll
    for (int i = 0; i < 8; i++) tot += red1[i];
    float mu = tot * (1.0f / 768.0f);

    float d0 = v0 - mu, d1 = v1 - mu, d2 = v2 - mu;
    float q = d0 * d0 + d1 * d1 + d2 * d2;
#pragma unroll
    for (int o = 16; o; o >>= 1) q += __shfl_xor_sync(0xffffffffu, q, o);
    if ((tid & 31) == 0) red2[tid >> 5] = q;
    __syncthreads();
    float qt = 0.f;
#pragma unroll
    for (int i = 0; i < 8; i++) qt += red2[i];
    float rstd = rsqrtf(qt * (1.0f / 768.0f) + 1e-5f);

    float* hr = h + (size_t)row * CC;
    size_t ob = (size_t)row * CC;
#pragma unroll
    for (int pI = 0; pI < 3; pI++) {
        int c = tid + pI * 256;
        float dd = (pI == 0) ? d0 : (pI == 1) ? d1 : d2;
        float nv = hr[c] + dd * rstd * g[c] + be[c];
        hr[c] = nv;
        __nv_bfloat16 hb = __float2bfloat16_rn(nv);
        hh[ob + c] = hb;
        hl[ob + c] = __float2bfloat16_rn(nv - __bfloat162float(hb));
    }
}

// ---------------------------------------------------------------------------
// Launch
// ---------------------------------------------------------------------------
extern "C" void kernel_launch(void* const* d_in, const int* in_sizes, int n_in,
                              void* d_out, int out_size)
{
    const int*   x     = (const int*)  d_in[0];
    const float* embed = (const float*)d_in[1];
    const float* pos   = (const float*)d_in[2];
    const float* Wqkv  = (const float*)d_in[3];
    const float* bqkv  = (const float*)d_in[4];
    const float* W1a   = (const float*)d_in[5];
    const float* b1a   = (const float*)d_in[6];
    const float* W2a   = (const float*)d_in[7];
    const float* b2a   = (const float*)d_in[8];
    const float* g1    = (const float*)d_in[9];
    const float* beta1 = (const float*)d_in[10];
    const float* W1b   = (const float*)d_in[11];
    const float* b1b   = (const float*)d_in[12];
    const float* W2b   = (const float*)d_in[13];
    const float* b2b   = (const float*)d_in[14];
    const float* g2    = (const float*)d_in[15];
    const float* beta2 = (const float*)d_in[16];
    const float* lmW   = (const float*)d_in[17];
    const float* lmb   = (const float*)d_in[18];
    float* out = (float*)d_out;

    float *h, *part;
    __nv_bfloat16 *hh, *hl, *qvh, *qvl, *ath, *atl, *mih, *mil;
    cudaGetSymbolAddress((void**)&h,    g_h);
    cudaGetSymbolAddress((void**)&part, g_part);
    cudaGetSymbolAddress((void**)&hh,   g_hh);
    cudaGetSymbolAddress((void**)&hl,   g_hl);
    cudaGetSymbolAddress((void**)&qvh,  g_qvh);
    cudaGetSymbolAddress((void**)&qvl,  g_qvl);
    cudaGetSymbolAddress((void**)&ath,  g_ath);
    cudaGetSymbolAddress((void**)&atl,  g_atl);
    cudaGetSymbolAddress((void**)&mih,  g_mih);
    cudaGetSymbolAddress((void**)&mil,  g_mil);

    __nv_bfloat16 *wqh, *wql, *w1ah, *w1al, *w2ah, *w2al,
                  *w1bh, *w1bl, *w2bh, *w2bl, *lmh, *lml;
    cudaGetSymbolAddress((void**)&wqh,  g_wqkv_h);
    cudaGetSymbolAddress((void**)&wql,  g_wqkv_l);
    cudaGetSymbolAddress((void**)&w1ah, g_w1a_h);
    cudaGetSymbolAddress((void**)&w1al, g_w1a_l);
    cudaGetSymbolAddress((void**)&w2ah, g_w2a_h);
    cudaGetSymbolAddress((void**)&w2al, g_w2a_l);
    cudaGetSymbolAddress((void**)&w1bh, g_w1b_h);
    cudaGetSymbolAddress((void**)&w1bl, g_w1b_l);
    cudaGetSymbolAddress((void**)&w2bh, g_w2b_h);
    cudaGetSymbolAddress((void**)&w2bl, g_w2b_l);
    cudaGetSymbolAddress((void**)&lmh,  g_lm_h);
    cudaGetSymbolAddress((void**)&lml,  g_lm_l);

    cudaFuncSetAttribute(hgemm_s4_kernel<0,0,1>,
        cudaFuncAttributeMaxDynamicSharedMemorySize, SMQ4);
    cudaFuncSetAttribute(hgemm_s4_kernel<1,0,1>,
        cudaFuncAttributeMaxDynamicSharedMemorySize, SMQ4);
    cudaFuncSetAttribute(hgemm_s4_kernel<0,1,0>,
        cudaFuncAttributeMaxDynamicSharedMemorySize, SMQ4);
    cudaFuncSetAttribute(hgemm_s4_pk_kernel,
        cudaFuncAttributeMaxDynamicSharedMemorySize, SMQ4);
    cudaFuncSetAttribute(attn_hmma_kernel,
        cudaFuncAttributeMaxDynamicSharedMemorySize, ASMEM);

    const dim3 cb(32, 8);
    // launch order keeps ncu capture (idx 3) on the first qkv GEMM
    convert_w_kernel<<<dim3(3 * CC / 32, CC / 32, LNUM), cb>>>(
        Wqkv, wqh, wql, CC, 3 * CC);                              // 0
    convert_w2_kernel<<<dim3(FFF / 32, CC / 32, 2 * LNUM), cb>>>(
        W1a, W1b, w1ah, w1al, w1bh, w1bl, CC, FFF);               // 1
    embed_kernel<<<BT, 192>>>(x, embed, pos, h, hh, hl);          // 2

    const dim3 grid_qkv (3 * CC / 64, BT / 128);
    const dim3 grid_ffn1(FFF / 64,    BT / 128);
    const dim3 grid_ffn2(CC / 64,     BT / 128, 2);   // split-K 2
    const dim3 grid_lm  (VV / 64,     BT / 128);
    const dim3 grid_attn(TT / 64, BB * HH);

    for (int l = 0; l < LNUM; l++) {
        hgemm_s4_kernel<0,0,1><<<grid_qkv, 128, SMQ4>>>(          // 3 (l=0)
            hh, hl, wqh + (size_t)l * 3 * CC * CC, wql + (size_t)l * 3 * CC * CC,
            bqkv + (size_t)l * 3 * CC, nullptr, qvh, qvl, 3 * CC, CC);
        attn_hmma_kernel<<<grid_attn, 128, ASMEM>>>(qvh, qvl, ath, atl);
        if (l == 0) {
            convert_w2_kernel<<<dim3(CC / 32, FFF / 32, 2 * LNUM), cb>>>(
                W2a, W2b, w2ah, w2al, w2bh, w2bl, FFF, CC);
        }
        hgemm_s4_kernel<1,0,1><<<grid_ffn1, 128, SMQ4>>>(
            ath, atl, w1ah + (size_t)l * CC * FFF, w1al + (size_t)l * CC * FFF,
            b1a + (size_t)l * FFF, nullptr, mih, mil, FFF, CC);
        hgemm_s4_pk_kernel<<<grid_ffn2, 128, SMQ4>>>(
            mih, mil, w2ah + (size_t)l * CC * FFF, w2al + (size_t)l * CC * FFF,
            part, BT, CC, FFF);
        ln_res2_kernel<<<BT, 256>>>(part, b2a + (size_t)l * CC,
                                    g1 + (size_t)l * CC,
                                    beta1 + (size_t)l * CC, h, hh, hl);
        hgemm_s4_kernel<1,0,1><<<grid_ffn1, 128, SMQ4>>>(
            hh, hl, w1bh + (size_t)l * CC * FFF, w1bl + (size_t)l * CC * FFF,
            b1b + (size_t)l * FFF, nullptr, mih, mil, FFF, CC);
        hgemm_s4_pk_kernel<<<grid_ffn2, 128, SMQ4>>>(
            mih, mil, w2bh + (size_t)l * CC * FFF, w2bl + (size_t)l * CC * FFF,
            part, BT, CC, FFF);
        ln_res2_kernel<<<BT, 256>>>(part, b2b + (size_t)l * CC,
                                    g2 + (size_t)l * CC,
                                    beta2 + (size_t)l * CC, h, hh, hl);
    }

    convert_w_kernel<<<dim3(VV / 32, CC / 32, 1), cb>>>(lmW, lmh, lml, CC, VV);
    hgemm_s4_kernel<0,1,0><<<grid_lm, 128, SMQ4>>>(
        hh, hl, lmh, lml, lmb, out, nullptr, nullptr, VV, CC);
}

// round 14
// speedup vs baseline: 1.0538x; 1.0068x over previous
#include <cuda_runtime.h>
#include <cuda_bf16.h>
#include <math.h>
#include <stdint.h>

#define LNUM 8
#define BB   8
#define TT   1024
#define CC   768
#define HH   12
#define DD   64
#define VV   1024
#define FFF  3072
#define BT   (BB*TT)   // 8192

// ---------------------------------------------------------------------------
// Scratch activations
// ---------------------------------------------------------------------------
__device__ float g_part[2 * BT * CC];          // FFN2 split-K partials
__device__ float g_h  [BT * CC];
__device__ __nv_bfloat16 g_hh [BT * CC];
__device__ __nv_bfloat16 g_hl [BT * CC];
__device__ __nv_bfloat16 g_qvh[BT * 3 * CC];
__device__ __nv_bfloat16 g_qvl[BT * 3 * CC];
__device__ __nv_bfloat16 g_ath[BT * CC];
__device__ __nv_bfloat16 g_atl[BT * CC];
__device__ __nv_bfloat16 g_mih[BT * FFF];
__device__ __nv_bfloat16 g_mil[BT * FFF];

// ---------------------------------------------------------------------------
// Pre-converted weights: transposed [N][K], bf16 hi/lo split
// ---------------------------------------------------------------------------
__device__ __nv_bfloat16 g_wqkv_h[LNUM * 3 * CC * CC];
__device__ __nv_bfloat16 g_wqkv_l[LNUM * 3 * CC * CC];
__device__ __nv_bfloat16 g_w1a_h [LNUM * CC * FFF];
__device__ __nv_bfloat16 g_w1a_l [LNUM * CC * FFF];
__device__ __nv_bfloat16 g_w2a_h [LNUM * CC * FFF];
__device__ __nv_bfloat16 g_w2a_l [LNUM * CC * FFF];
__device__ __nv_bfloat16 g_w1b_h [LNUM * CC * FFF];
__device__ __nv_bfloat16 g_w1b_l [LNUM * CC * FFF];
__device__ __nv_bfloat16 g_w2b_h [LNUM * CC * FFF];
__device__ __nv_bfloat16 g_w2b_l [LNUM * CC * FFF];
__device__ __nv_bfloat16 g_lm_h  [VV * CC];
__device__ __nv_bfloat16 g_lm_l  [VV * CC];

// ---------------------------------------------------------------------------
// Helpers
// ---------------------------------------------------------------------------
__device__ __forceinline__ float gelu_f(float x) {
    return 0.5f * x * (1.0f + erff(x * 0.70710678118654752f));
}

__device__ __forceinline__ uint32_t smem_u32(const void* p) {
    uint32_t a;
    asm("{ .reg .u64 t; cvta.to.shared.u64 t, %1; cvt.u32.u64 %0, t; }"
        : "=r"(a) : "l"(p));
    return a;
}

__device__ __forceinline__ void cpa16(uint32_t s, const void* g) {
    asm volatile("cp.async.cg.shared.global [%0], [%1], 16;"
                 :: "r"(s), "l"(g));
}
#define CP_COMMIT() asm volatile("cp.async.commit_group;" ::: "memory")
#define CP_WAIT1()  asm volatile("cp.async.wait_group 1;" ::: "memory")
#define CP_WAIT0()  asm volatile("cp.async.wait_group 0;" ::: "memory")

__device__ __forceinline__ void ldsm4(uint32_t* r, uint32_t a) {
    asm volatile("ldmatrix.sync.aligned.m8n8.x4.shared.b16 {%0,%1,%2,%3}, [%4];"
        : "=r"(r[0]), "=r"(r[1]), "=r"(r[2]), "=r"(r[3]) : "r"(a));
}
__device__ __forceinline__ void ldsm4t(uint32_t* r, uint32_t a) {
    asm volatile("ldmatrix.sync.aligned.m8n8.x4.trans.shared.b16 {%0,%1,%2,%3}, [%4];"
        : "=r"(r[0]), "=r"(r[1]), "=r"(r[2]), "=r"(r[3]) : "r"(a));
}

__device__ __forceinline__ void mma16816(float* c, const uint32_t* a,
                                         uint32_t b0, uint32_t b1) {
    asm volatile(
        "mma.sync.aligned.m16n8k16.row.col.f32.bf16.bf16.f32 "
        "{%0,%1,%2,%3}, {%4,%5,%6,%7}, {%8,%9}, {%0,%1,%2,%3};"
        : "+f"(c[0]), "+f"(c[1]), "+f"(c[2]), "+f"(c[3])
        : "r"(a[0]), "r"(a[1]), "r"(a[2]), "r"(a[3]), "r"(b0), "r"(b1));
}

__device__ __forceinline__ uint32_t pack_bf2(float a, float b) {
    __nv_bfloat162 p = __floats2bfloat162_rn(a, b);
    return *reinterpret_cast<uint32_t*>(&p);
}
__device__ __forceinline__ void split2(float v0, float v1,
                                       uint32_t& hp, uint32_t& lp) {
    __nv_bfloat16 h0 = __float2bfloat16_rn(v0);
    __nv_bfloat16 h1 = __float2bfloat16_rn(v1);
    float l0 = v0 - __bfloat162float(h0);
    float l1 = v1 - __bfloat162float(h1);
    __nv_bfloat162 hh = __halves2bfloat162(h0, h1);
    hp = *reinterpret_cast<uint32_t*>(&hh);
    lp = pack_bf2(l0, l1);
}

// GEMM smem swizzle: 64B rows, 4 chunks of 16B, chunk ^= (row>>1)&3
__device__ __forceinline__ uint32_t swz(int row, int c) {
    return (uint32_t)((row << 6) + (((c ^ ((row >> 1) & 3)) << 4)));
}
// Attention smem swizzle: 128B rows, 8 chunks of 16B, chunk ^= row&7
__device__ __forceinline__ uint32_t swz8(int row, int c) {
    return (uint32_t)((row << 7) + (((c ^ (row & 7)) << 4)));
}

// ---------------------------------------------------------------------------
// Weight pre-convert
// ---------------------------------------------------------------------------
__device__ __forceinline__ void convert_body(
    const float* __restrict__ Wl, __nv_bfloat16* __restrict__ hl,
    __nv_bfloat16* __restrict__ ll, int K, int N)
{
    __shared__ float t[32][33];
    const int kb = blockIdx.y << 5, nb = blockIdx.x << 5;
    const int tx = threadIdx.x, ty = threadIdx.y;
#pragma unroll
    for (int i = 0; i < 32; i += 8)
        t[ty + i][tx] = Wl[(size_t)(kb + ty + i) * N + nb + tx];
    __syncthreads();
#pragma unroll
    for (int i = 0; i < 32; i += 8) {
        float v = t[tx][ty + i];
        __nv_bfloat16 h = __float2bfloat16_rn(v);
        __nv_bfloat16 l = __float2bfloat16_rn(v - __bfloat162float(h));
        size_t o = (size_t)(nb + ty + i) * K + kb + tx;
        hl[o] = h; ll[o] = l;
    }
}

__global__ void __launch_bounds__(256) convert_w_kernel(
    const float* __restrict__ W, __nv_bfloat16* __restrict__ hi,
    __nv_bfloat16* __restrict__ lo, int K, int N)
{
    const size_t loff = (size_t)blockIdx.z * K * N;
    convert_body(W + loff, hi + loff, lo + loff, K, N);
}

__global__ void __launch_bounds__(256) convert_w2_kernel(
    const float* __restrict__ Wa, const float* __restrict__ Wb,
    __nv_bfloat16* __restrict__ hia, __nv_bfloat16* __restrict__ loa,
    __nv_bfloat16* __restrict__ hib, __nv_bfloat16* __restrict__ lob,
    int K, int N)
{
    int z = blockIdx.z;
    const float* W; __nv_bfloat16 *hi, *lo;
    if (z < LNUM) {
        size_t o = (size_t)z * K * N;
        W = Wa + o; hi = hia + o; lo = loa + o;
    } else {
        size_t o = (size_t)(z - LNUM) * K * N;
        W = Wb + o; hi = hib + o; lo = lob + o;
    }
    convert_body(W, hi, lo, K, N);
}

// ---------------------------------------------------------------------------
// HMMA GEMM S4 (R11/R13 config): 128x64 CTA tile, 128 threads (4 warps in M),
// 2-stage pipeline, 48KB smem -> 4 CTAs/SM.
// ---------------------------------------------------------------------------
#define TA4 (128 * 64)                  // 8192 B
#define TB4 (64 * 64)                   // 4096 B
#define STG4 (2 * TA4 + 2 * TB4)        // 24576 B
#define SMQ4 (2 * STG4)                 // 49152 B

template<int EPI, int WF32, int WHL>
__global__ void __launch_bounds__(128, 4) hgemm_s4_kernel(
    const __nv_bfloat16* __restrict__ Ah, const __nv_bfloat16* __restrict__ Al,
    const __nv_bfloat16* __restrict__ Bh, const __nv_bfloat16* __restrict__ Bl,
    const float* __restrict__ bias, float* __restrict__ C,
    __nv_bfloat16* __restrict__ Ch, __nv_bfloat16* __restrict__ Cl,
    int N, int K)
{
    extern __shared__ __align__(128) char smem[];
    const int tid  = threadIdx.x;
    const int lane = tid & 31;
    const int wid  = tid >> 5;
    const int g    = lane >> 2, t = lane & 3;
    const int bm   = blockIdx.y << 7, bn = blockIdx.x << 6;
    const uint32_t sbase = smem_u32(smem);

    const __nv_bfloat16* gpA[2] = { Ah + (size_t)bm * K, Al + (size_t)bm * K };
    const __nv_bfloat16* gpB[2] = { Bh + (size_t)bn * K, Bl + (size_t)bn * K };

    float acc[2][8][4];
#pragma unroll
    for (int mi = 0; mi < 2; mi++)
#pragma unroll
        for (int ni = 0; ni < 8; ni++)
#pragma unroll
            for (int r = 0; r < 4; r++) acc[mi][ni][r] = 0.f;

    const int nk = K >> 5;
    const int srow = tid >> 2, schk = tid & 3;

    auto stage = [&](int kt, int buf) {
        uint32_t s0 = sbase + buf * STG4;
        const int kc = kt * 32 + schk * 8;
#pragma unroll
        for (int m = 0; m < 2; m++) {
#pragma unroll
            for (int i = 0; i < 4; i++) {
                int row = srow + i * 32;
                cpa16(s0 + m * TA4 + swz(row, schk),
                      gpA[m] + (size_t)row * K + kc);
            }
#pragma unroll
            for (int i = 0; i < 2; i++) {
                int row = srow + i * 32;
                cpa16(s0 + 2 * TA4 + m * TB4 + swz(row, schk),
                      gpB[m] + (size_t)row * K + kc);
            }
        }
        CP_COMMIT();
    };

    stage(0, 0);
    stage(1, 1);

    const int arow0 = wid * 32 + (lane & 15);
    const int akh   = lane >> 4;
    const int brow0 = (lane & 7) + ((lane >> 4) << 3);
    const int bkh   = (lane >> 3) & 1;

    for (int kt = 0; kt < nk; kt++) {
        CP_WAIT1();
        __syncthreads();

        const uint32_t st  = sbase + (kt & 1) * STG4;
        const uint32_t Ahp = st, Alp = st + TA4;
        const uint32_t Bhp = st + 2 * TA4, Blp = st + 2 * TA4 + TB4;

#pragma unroll
        for (int ks = 0; ks < 2; ks++) {
            uint32_t ah[2][4], al[2][4];
#pragma unroll
            for (int mi = 0; mi < 2; mi++) {
                int row = arow0 + mi * 16;
                uint32_t ao = swz(row, ks * 2 + akh);
                ldsm4(ah[mi], Ahp + ao);
                ldsm4(al[mi], Alp + ao);
            }
#pragma unroll
            for (int nip = 0; nip < 4; nip++) {
                int row = brow0 + nip * 16;
                uint32_t bo = swz(row, ks * 2 + bkh);
                uint32_t bh[4], bl[4];
                ldsm4(bh, Bhp + bo);
                ldsm4(bl, Blp + bo);
#pragma unroll
                for (int mi = 0; mi < 2; mi++) {
                    mma16816(acc[mi][2 * nip],     ah[mi], bh[0], bh[1]);
                    mma16816(acc[mi][2 * nip + 1], ah[mi], bh[2], bh[3]);
                }
#pragma unroll
                for (int mi = 0; mi < 2; mi++) {
                    mma16816(acc[mi][2 * nip],     ah[mi], bl[0], bl[1]);
                    mma16816(acc[mi][2 * nip + 1], ah[mi], bl[2], bl[3]);
                }
#pragma unroll
                for (int mi = 0; mi < 2; mi++) {
                    mma16816(acc[mi][2 * nip],     al[mi], bh[0], bh[1]);
                    mma16816(acc[mi][2 * nip + 1], al[mi], bh[2], bh[3]);
                }
            }
        }

        __syncthreads();
        if (kt + 2 < nk) stage(kt + 2, kt & 1); else CP_COMMIT();
    }

#pragma unroll
    for (int ni = 0; ni < 8; ni++) {
        int col = bn + ni * 8 + t * 2;
        float b0 = bias[col], b1 = bias[col + 1];
#pragma unroll
        for (int mi = 0; mi < 2; mi++) {
            int r0 = bm + wid * 32 + mi * 16 + g;
            float v0 = acc[mi][ni][0] + b0;
            float v1 = acc[mi][ni][1] + b1;
            float v2 = acc[mi][ni][2] + b0;
            float v3 = acc[mi][ni][3] + b1;
            if (EPI == 1) {
                v0 = gelu_f(v0); v1 = gelu_f(v1);
                v2 = gelu_f(v2); v3 = gelu_f(v3);
            }
            size_t o0 = (size_t)r0 * N + col;
            size_t o1 = (size_t)(r0 + 8) * N + col;
            if (WF32) {
                *(float2*)(C + o0) = make_float2(v0, v1);
                *(float2*)(C + o1) = make_float2(v2, v3);
            }
            if (WHL) {
                uint32_t hp, lp;
                split2(v0, v1, hp, lp);
                *(uint32_t*)(Ch + o0) = hp;
                *(uint32_t*)(Cl + o0) = lp;
                split2(v2, v3, hp, lp);
                *(uint32_t*)(Ch + o1) = hp;
                *(uint32_t*)(Cl + o1) = lp;
            }
        }
    }
}

// ---------------------------------------------------------------------------
// HMMA GEMM S4 split-K2 partial (FFN2)
// ---------------------------------------------------------------------------
__global__ void __launch_bounds__(128, 4) hgemm_s4_pk_kernel(
    const __nv_bfloat16* __restrict__ Ah, const __nv_bfloat16* __restrict__ Al,
    const __nv_bfloat16* __restrict__ Bh, const __nv_bfloat16* __restrict__ Bl,
    float* __restrict__ P, int M, int N, int K)
{
    extern __shared__ __align__(128) char smem[];
    const int tid  = threadIdx.x;
    const int lane = tid & 31;
    const int wid  = tid >> 5;
    const int g    = lane >> 2, t = lane & 3;
    const int bm   = blockIdx.y << 7, bn = blockIdx.x << 6;
    const int z    = blockIdx.z;
    const int Kh   = K >> 1;
    const int kc0  = z * Kh;
    const uint32_t sbase = smem_u32(smem);

    const __nv_bfloat16* gpA[2] = { Ah + (size_t)bm * K + kc0,
                                    Al + (size_t)bm * K + kc0 };
    const __nv_bfloat16* gpB[2] = { Bh + (size_t)bn * K + kc0,
                                    Bl + (size_t)bn * K + kc0 };

    float acc[2][8][4];
#pragma unroll
    for (int mi = 0; mi < 2; mi++)
#pragma unroll
        for (int ni = 0; ni < 8; ni++)
#pragma unroll
            for (int r = 0; r < 4; r++) acc[mi][ni][r] = 0.f;

    const int nk = Kh >> 5;
    const int srow = tid >> 2, schk = tid & 3;

    auto stage = [&](int kt, int buf) {
        uint32_t s0 = sbase + buf * STG4;
        const int kc = kt * 32 + schk * 8;
#pragma unroll
        for (int m = 0; m < 2; m++) {
#pragma unroll
            for (int i = 0; i < 4; i++) {
                int row = srow + i * 32;
                cpa16(s0 + m * TA4 + swz(row, schk),
                      gpA[m] + (size_t)row * K + kc);
            }
#pragma unroll
            for (int i = 0; i < 2; i++) {
                int row = srow + i * 32;
                cpa16(s0 + 2 * TA4 + m * TB4 + swz(row, schk),
                      gpB[m] + (size_t)row * K + kc);
            }
        }
        CP_COMMIT();
    };

    stage(0, 0);
    stage(1, 1);

    const int arow0 = wid * 32 + (lane & 15);
    const int akh   = lane >> 4;
    const int brow0 = (lane & 7) + ((lane >> 4) << 3);
    const int bkh   = (lane >> 3) & 1;

    for (int kt = 0; kt < nk; kt++) {
        CP_WAIT1();
        __syncthreads();

        const uint32_t st  = sbase + (kt & 1) * STG4;
        const uint32_t Ahp = st, Alp = st + TA4;
        const uint32_t Bhp = st + 2 * TA4, Blp = st + 2 * TA4 + TB4;

#pragma unroll
        for (int ks = 0; ks < 2; ks++) {
            uint32_t ah[2][4], al[2][4];
#pragma unroll
            for (int mi = 0; mi < 2; mi++) {
                int row = arow0 + mi * 16;
                uint32_t ao = swz(row, ks * 2 + akh);
                ldsm4(ah[mi], Ahp + ao);
                ldsm4(al[mi], Alp + ao);
            }
#pragma unroll
            for (int nip = 0; nip < 4; nip++) {
                int row = brow0 + nip * 16;
                uint32_t bo = swz(row, ks * 2 + bkh);
                uint32_t bh[4], bl[4];
                ldsm4(bh, Bhp + bo);
                ldsm4(bl, Blp + bo);
#pragma unroll
                for (int mi = 0; mi < 2; mi++) {
                    mma16816(acc[mi][2 * nip],     ah[mi], bh[0], bh[1]);
                    mma16816(acc[mi][2 * nip + 1], ah[mi], bh[2], bh[3]);
                }
#pragma unroll
                for (int mi = 0; mi < 2; mi++) {
                    mma16816(acc[mi][2 * nip],     ah[mi], bl[0], bl[1]);
                    mma16816(acc[mi][2 * nip + 1], ah[mi], bl[2], bl[3]);
                }
#pragma unroll
                for (int mi = 0; mi < 2; mi++) {
                    mma16816(acc[mi][2 * nip],     al[mi], bh[0], bh[1]);
                    mma16816(acc[mi][2 * nip + 1], al[mi], bh[2], bh[3]);
                }
            }
        }

        __syncthreads();
        if (kt + 2 < nk) stage(kt + 2, kt & 1); else CP_COMMIT();
    }

    float* Pz = P + (size_t)z * M * N;
#pragma unroll
    for (int ni = 0; ni < 8; ni++) {
        int col = bn + ni * 8 + t * 2;
#pragma unroll
        for (int mi = 0; mi < 2; mi++) {
            int r0 = bm + wid * 32 + mi * 16 + g;
            *(float2*)(Pz + (size_t)r0 * N + col) =
                make_float2(acc[mi][ni][0], acc[mi][ni][1]);
            *(float2*)(Pz + (size_t)(r0 + 8) * N + col) =
                make_float2(acc[mi][ni][2], acc[mi][ni][3]);
        }
    }
}

// ---------------------------------------------------------------------------
// Embedding
// ---------------------------------------------------------------------------
__global__ void __launch_bounds__(192) embed_kernel(
    const int* __restrict__ x, const float* __restrict__ emb,
    const float* __restrict__ pos, float* __restrict__ h,
    __nv_bfloat16* __restrict__ hh, __nv_bfloat16* __restrict__ hl)
{
    const int bt  = blockIdx.x;
    const int tok = x[bt];
    const int t   = bt & (TT - 1);
    const float4* e4 = (const float4*)(emb + (size_t)tok * CC);
    const float4* p4 = (const float4*)(pos + (size_t)t   * CC);
    const int i = threadIdx.x;
    float4 a = e4[i], b = p4[i];
    float4 s = make_float4(a.x + b.x, a.y + b.y, a.z + b.z, a.w + b.w);
    ((float4*)(h + (size_t)bt * CC))[i] = s;
    size_t o = (size_t)bt * CC + i * 4;
    uint32_t hp, lp;
    split2(s.x, s.y, hp, lp);
    *(uint32_t*)(hh + o) = hp;     *(uint32_t*)(hl + o) = lp;
    split2(s.z, s.w, hp, lp);
    *(uint32_t*)(hh + o + 2) = hp; *(uint32_t*)(hl + o + 2) = lp;
}

// ---------------------------------------------------------------------------
// HMMA flash attention v3: cp.async KV double-buffer, ONE barrier per k-tile.
// SMEM (96KB): Qh 0 | Ql 8K | Ph 16K | Pl 24K
//              | KV buf b at 32K + b*32K : Kh | Kl | Vh | Vl (8K each)
// Loop: wait0; barrier; stage(kt+1)->buf (kt+1)&1; compute buf kt&1.
// Safety: buf (kt+1)&1 last read in iter kt-1, whose reads precede this
// iter's barrier for every thread (program order + barrier).
// ---------------------------------------------------------------------------
#define ASMEM (96 * 1024)

__global__ void __launch_bounds__(128) attn_hmma_kernel(
    const __nv_bfloat16* __restrict__ qkvh,
    const __nv_bfloat16* __restrict__ qkvl,
    __nv_bfloat16* __restrict__ outh, __nv_bfloat16* __restrict__ outl)
{
    extern __shared__ __align__(128) char asmem[];
    const int tid  = threadIdx.x;
    const int lane = tid & 31, wid = tid >> 5;
    const int g    = lane >> 2, t = lane & 3;
    const int qtile = blockIdx.x, bh = blockIdx.y;
    const int b = bh / HH, h = bh % HH;
    const int qb = qtile << 6;
    const uint32_t S = smem_u32(asmem);
    const size_t bbase = (size_t)b * TT * 3 * CC;

    auto stage64 = [&](uint32_t off, const __nv_bfloat16* src,
                       int tok0, int coff) {
#pragma unroll
        for (int i = 0; i < 4; i++) {
            int idx = tid + (i << 7);
            int row = idx >> 3, chk = idx & 7;
            cpa16(S + off + swz8(row, chk),
                  src + bbase + (size_t)(tok0 + row) * (3 * CC)
                      + coff + chk * 8);
        }
    };
    auto stageKV = [&](int kb, int buf) {
        uint32_t base = 32768 + buf * 32768;
        stage64(base,         qkvh, kb, h * 64);           // Kh
        stage64(base + 8192,  qkvl, kb, h * 64);           // Kl
        stage64(base + 16384, qkvh, kb, 2 * CC + h * 64);  // Vh
        stage64(base + 24576, qkvl, kb, 2 * CC + h * 64);  // Vl
        CP_COMMIT();
    };

    // stage Q (group 0), KV tile 0 (group 1)
    stage64(0,    qkvh, qb, CC + h * 64);
    stage64(8192, qkvl, qb, CC + h * 64);
    CP_COMMIT();
    stageKV(0, 0);

    // Q fragments (wait for Q group only; KV0 may still be in flight)
    CP_WAIT1();
    __syncthreads();
    uint32_t qh[4][4], ql[4][4];
    {
        int row = wid * 16 + (lane & 15);
        int kh  = lane >> 4;
#pragma unroll
        for (int ks = 0; ks < 4; ks++) {
            uint32_t ao = swz8(row, ks * 2 + kh);
            ldsm4(qh[ks], S + 0 + ao);
            ldsm4(ql[ks], S + 8192 + ao);
        }
    }

    float O[8][4];
#pragma unroll
    for (int ni = 0; ni < 8; ni++)
#pragma unroll
        for (int r = 0; r < 4; r++) O[ni][r] = 0.f;
    float m0 = -1e30f, m1 = -1e30f, l0 = 0.f, l1 = 0.f;

    const int row0a = qb + wid * 16 + g;
    const int row1a = row0a + 8;

    for (int kt = 0; kt <= qtile; kt++) {
        const int kb = kt << 6;
        CP_WAIT0();            // KV(kt) complete (newest committed group)
        __syncthreads();       // visibility + prior-iter reads of other buf done
        if (kt < qtile) stageKV(kb + 64, (kt + 1) & 1);   // overlaps compute

        const uint32_t KB  = S + 32768 + (kt & 1) * 32768;
        const uint32_t Khp = KB, Klp = KB + 8192;
        const uint32_t Vhp = KB + 16384, Vlp = KB + 24576;

        float sa[8][4];
#pragma unroll
        for (int ni = 0; ni < 8; ni++)
#pragma unroll
            for (int r = 0; r < 4; r++) sa[ni][r] = 0.f;
        {
            int brow = (lane & 7) + ((lane >> 4) << 3);
            int bkh  = (lane >> 3) & 1;
#pragma unroll
            for (int ks = 0; ks < 4; ks++) {
#pragma unroll
                for (int nip = 0; nip < 4; nip++) {
                    uint32_t bo = swz8(nip * 16 + brow, ks * 2 + bkh);
                    uint32_t kh_[4], kl_[4];
                    ldsm4(kh_, Khp + bo);
                    ldsm4(kl_, Klp + bo);
                    mma16816(sa[2 * nip],     qh[ks], kh_[0], kh_[1]);
                    mma16816(sa[2 * nip + 1], qh[ks], kh_[2], kh_[3]);
                    mma16816(sa[2 * nip],     qh[ks], kl_[0], kl_[1]);
                    mma16816(sa[2 * nip + 1], qh[ks], kl_[2], kl_[3]);
                    mma16816(sa[2 * nip],     ql[ks], kh_[0], kh_[1]);
                    mma16816(sa[2 * nip + 1], ql[ks], kh_[2], kh_[3]);
                }
            }
        }

        const bool diag = (kt == qtile);
#pragma unroll
        for (int ni = 0; ni < 8; ni++) {
            int c0 = kb + ni * 8 + t * 2, c1 = c0 + 1;
            sa[ni][0] *= 0.125f; sa[ni][1] *= 0.125f;
            sa[ni][2] *= 0.125f; sa[ni][3] *= 0.125f;
            if (diag) {
                if (c0 > row0a) sa[ni][0] = -1e30f;
                if (c1 > row0a) sa[ni][1] = -1e30f;
                if (c0 > row1a) sa[ni][2] = -1e30f;
                if (c1 > row1a) sa[ni][3] = -1e30f;
            }
        }

        float pm0 = -1e30f, pm1 = -1e30f;
#pragma unroll
        for (int ni = 0; ni < 8; ni++) {
            pm0 = fmaxf(pm0, fmaxf(sa[ni][0], sa[ni][1]));
            pm1 = fmaxf(pm1, fmaxf(sa[ni][2], sa[ni][3]));
        }
#pragma unroll
        for (int o = 1; o < 4; o <<= 1) {
            pm0 = fmaxf(pm0, __shfl_xor_sync(0xffffffffu, pm0, o));
            pm1 = fmaxf(pm1, __shfl_xor_sync(0xffffffffu, pm1, o));
        }
        float mn0 = fmaxf(m0, pm0), mn1 = fmaxf(m1, pm1);
        float a0 = __expf(m0 - mn0), a1 = __expf(m1 - mn1);
        m0 = mn0; m1 = mn1;

        float rs0 = 0.f, rs1 = 0.f;
        const int prow0 = wid * 16 + g, prow1 = prow0 + 8;
#pragma unroll
        for (int ni = 0; ni < 8; ni++) {
            float p0 = __expf(sa[ni][0] - mn0);
            float p1 = __expf(sa[ni][1] - mn0);
            float p2 = __expf(sa[ni][2] - mn1);
            float p3 = __expf(sa[ni][3] - mn1);
            rs0 += p0 + p1; rs1 += p2 + p3;
            uint32_t hp, lp;
            split2(p0, p1, hp, lp);
            *(uint32_t*)(asmem + 16384 + (prow0 << 7)
                         + ((ni ^ (prow0 & 7)) << 4) + t * 4) = hp;
            *(uint32_t*)(asmem + 24576 + (prow0 << 7)
                         + ((ni ^ (prow0 & 7)) << 4) + t * 4) = lp;
            split2(p2, p3, hp, lp);
            *(uint32_t*)(asmem + 16384 + (prow1 << 7)
                         + ((ni ^ (prow1 & 7)) << 4) + t * 4) = hp;
            *(uint32_t*)(asmem + 24576 + (prow1 << 7)
                         + ((ni ^ (prow1 & 7)) << 4) + t * 4) = lp;
        }
#pragma unroll
        for (int o = 1; o < 4; o <<= 1) {
            rs0 += __shfl_xor_sync(0xffffffffu, rs0, o);
            rs1 += __shfl_xor_sync(0xffffffffu, rs1, o);
        }
        l0 = l0 * a0 + rs0;
        l1 = l1 * a1 + rs1;
#pragma unroll
        for (int ni = 0; ni < 8; ni++) {
            O[ni][0] *= a0; O[ni][1] *= a0;
            O[ni][2] *= a1; O[ni][3] *= a1;
        }
        __syncwarp();   // P rows are warp-private

        {
            int arow = wid * 16 + (lane & 15);
            int akh2 = lane >> 4;
            int vrow = (lane & 7) + (((lane >> 3) & 1) << 3);
            int vch  = lane >> 4;
#pragma unroll
            for (int ks = 0; ks < 4; ks++) {
                uint32_t ao = swz8(arow, ks * 2 + akh2);
                uint32_t ph_[4], pl_[4];
                ldsm4(ph_, S + 16384 + ao);
                ldsm4(pl_, S + 24576 + ao);
#pragma unroll
                for (int nip = 0; nip < 4; nip++) {
                    uint32_t vo = swz8(ks * 16 + vrow, nip * 2 + vch);
                    uint32_t vh_[4], vl_[4];
                    ldsm4t(vh_, Vhp + vo);
                    ldsm4t(vl_, Vlp + vo);
                    mma16816(O[2 * nip],     ph_, vh_[0], vh_[1]);
                    mma16816(O[2 * nip + 1], ph_, vh_[2], vh_[3]);
                    mma16816(O[2 * nip],     ph_, vl_[0], vl_[1]);
                    mma16816(O[2 * nip + 1], ph_, vl_[2], vl_[3]);
                    mma16816(O[2 * nip],     pl_, vh_[0], vh_[1]);
                    mma16816(O[2 * nip + 1], pl_, vh_[2], vh_[3]);
                }
            }
        }
    }

    float inv0 = 1.0f / l0, inv1 = 1.0f / l1;
    const size_t gr0 = ((size_t)b * TT + row0a) * CC + h * 64;
    const size_t gr1 = ((size_t)b * TT + row1a) * CC + h * 64;
#pragma unroll
    for (int ni = 0; ni < 8; ni++) {
        int col = ni * 8 + t * 2;
        uint32_t hp, lp;
        split2(O[ni][0] * inv0, O[ni][1] * inv0, hp, lp);
        *(uint32_t*)(outh + gr0 + col) = hp;
        *(uint32_t*)(outl + gr0 + col) = lp;
        split2(O[ni][2] * inv1, O[ni][3] * inv1, hp, lp);
        *(uint32_t*)(outh + gr1 + col) = hp;
        *(uint32_t*)(outl + gr1 + col) = lp;
    }
}

// ---------------------------------------------------------------------------
// Fused split-K reduce + bias + LayerNorm + residual
// ---------------------------------------------------------------------------
__global__ void __launch_bounds__(256) ln_res2_kernel(
    const float* __restrict__ p, const float* __restrict__ bias,
    const float* __restrict__ g, const float* __restrict__ be,
    float* __restrict__ h,
    __nv_bfloat16* __restrict__ hh, __nv_bfloat16* __restrict__ hl)
{
    __shared__ float red1[8];
    __shared__ float red2[8];
    const int row = blockIdx.x;
    const int tid = threadIdx.x;
    const float* p0 = p + (size_t)row * CC;
    const float* p1 = p + (size_t)BT * CC + (size_t)row * CC;

    float v0 = p0[tid]       + p1[tid]       + bias[tid];
    float v1 = p0[tid + 256] + p1[tid + 256] + bias[tid + 256];
    float v2 = p0[tid + 512] + p1[tid + 512] + bias[tid + 512];
    float s = v0 + v1 + v2;
#pragma unroll
    for (int o = 16; o; o >>= 1) s += __shfl_xor_sync(0xffffffffu, s, o);
    if ((tid & 31) == 0) red1[tid >> 5] = s;
    __syncthreads();
    float tot = 0.f;
#pragma unroll
    for (int i = 0; i < 8; i++) tot += red1[i];
    float mu = tot * (1.0f / 768.0f);

    float d0 = v0 - mu, d1 = v1 - mu, d2 = v2 - mu;
    float q = d0 * d0 + d1 * d1 + d2 * d2;
#pragma unroll
    for (int o = 16; o; o >>= 1) q += __shfl_xor_sync(0xffffffffu, q, o);
    if ((tid & 31) == 0) red2[tid >> 5] = q;
    __syncthreads();
    float qt = 0.f;
#pragma unroll
    for (int i = 0; i < 8; i++) qt += red2[i];
    float rstd = rsqrtf(qt * (1.0f / 768.0f) + 1e-5f);

    float* hr = h + (size_t)row * CC;
    size_t ob = (size_t)row * CC;
#pragma unroll
    for (int pI = 0; pI < 3; pI++) {
        int c = tid + pI * 256;
        float dd = (pI == 0) ? d0 : (pI == 1) ? d1 : d2;
        float nv = hr[c] + dd * rstd * g[c] + be[c];
        hr[c] = nv;
        __nv_bfloat16 hb = __float2bfloat16_rn(nv);
        hh[ob + c] = hb;
        hl[ob + c] = __float2bfloat16_rn(nv - __bfloat162float(hb));
    }
}

// ---------------------------------------------------------------------------
// Launch
// ---------------------------------------------------------------------------
extern "C" void kernel_launch(void* const* d_in, const int* in_sizes, int n_in,
                              void* d_out, int out_size)
{
    const int*   x     = (const int*)  d_in[0];
    const float* embed = (const float*)d_in[1];
    const float* pos   = (const float*)d_in[2];
    const float* Wqkv  = (const float*)d_in[3];
    const float* bqkv  = (const float*)d_in[4];
    const float* W1a   = (const float*)d_in[5];
    const float* b1a   = (const float*)d_in[6];
    const float* W2a   = (const float*)d_in[7];
    const float* b2a   = (const float*)d_in[8];
    const float* g1    = (const float*)d_in[9];
    const float* beta1 = (const float*)d_in[10];
    const float* W1b   = (const float*)d_in[11];
    const float* b1b   = (const float*)d_in[12];
    const float* W2b   = (const float*)d_in[13];
    const float* b2b   = (const float*)d_in[14];
    const float* g2    = (const float*)d_in[15];
    const float* beta2 = (const float*)d_in[16];
    const float* lmW   = (const float*)d_in[17];
    const float* lmb   = (const float*)d_in[18];
    float* out = (float*)d_out;

    float *h, *part;
    __nv_bfloat16 *hh, *hl, *qvh, *qvl, *ath, *atl, *mih, *mil;
    cudaGetSymbolAddress((void**)&h,    g_h);
    cudaGetSymbolAddress((void**)&part, g_part);
    cudaGetSymbolAddress((void**)&hh,   g_hh);
    cudaGetSymbolAddress((void**)&hl,   g_hl);
    cudaGetSymbolAddress((void**)&qvh,  g_qvh);
    cudaGetSymbolAddress((void**)&qvl,  g_qvl);
    cudaGetSymbolAddress((void**)&ath,  g_ath);
    cudaGetSymbolAddress((void**)&atl,  g_atl);
    cudaGetSymbolAddress((void**)&mih,  g_mih);
    cudaGetSymbolAddress((void**)&mil,  g_mil);

    __nv_bfloat16 *wqh, *wql, *w1ah, *w1al, *w2ah, *w2al,
                  *w1bh, *w1bl, *w2bh, *w2bl, *lmh, *lml;
    cudaGetSymbolAddress((void**)&wqh,  g_wqkv_h);
    cudaGetSymbolAddress((void**)&wql,  g_wqkv_l);
    cudaGetSymbolAddress((void**)&w1ah, g_w1a_h);
    cudaGetSymbolAddress((void**)&w1al, g_w1a_l);
    cudaGetSymbolAddress((void**)&w2ah, g_w2a_h);
    cudaGetSymbolAddress((void**)&w2al, g_w2a_l);
    cudaGetSymbolAddress((void**)&w1bh, g_w1b_h);
    cudaGetSymbolAddress((void**)&w1bl, g_w1b_l);
    cudaGetSymbolAddress((void**)&w2bh, g_w2b_h);
    cudaGetSymbolAddress((void**)&w2bl, g_w2b_l);
    cudaGetSymbolAddress((void**)&lmh,  g_lm_h);
    cudaGetSymbolAddress((void**)&lml,  g_lm_l);

    cudaFuncSetAttribute(hgemm_s4_kernel<0,0,1>,
        cudaFuncAttributeMaxDynamicSharedMemorySize, SMQ4);
    cudaFuncSetAttribute(hgemm_s4_kernel<1,0,1>,
        cudaFuncAttributeMaxDynamicSharedMemorySize, SMQ4);
    cudaFuncSetAttribute(hgemm_s4_kernel<0,1,0>,
        cudaFuncAttributeMaxDynamicSharedMemorySize, SMQ4);
    cudaFuncSetAttribute(hgemm_s4_pk_kernel,
        cudaFuncAttributeMaxDynamicSharedMemorySize, SMQ4);
    cudaFuncSetAttribute(attn_hmma_kernel,
        cudaFuncAttributeMaxDynamicSharedMemorySize, ASMEM);

    const dim3 cb(32, 8);
    // launch order keeps ncu capture (idx 3) on the first qkv GEMM
    convert_w_kernel<<<dim3(3 * CC / 32, CC / 32, LNUM), cb>>>(
        Wqkv, wqh, wql, CC, 3 * CC);                              // 0
    convert_w2_kernel<<<dim3(FFF / 32, CC / 32, 2 * LNUM), cb>>>(
        W1a, W1b, w1ah, w1al, w1bh, w1bl, CC, FFF);               // 1
    embed_kernel<<<BT, 192>>>(x, embed, pos, h, hh, hl);          // 2

    const dim3 grid_qkv (3 * CC / 64, BT / 128);
    const dim3 grid_ffn1(FFF / 64,    BT / 128);
    const dim3 grid_ffn2(CC / 64,     BT / 128, 2);   // split-K 2
    const dim3 grid_lm  (VV / 64,     BT / 128);
    const dim3 grid_attn(TT / 64, BB * HH);

    for (int l = 0; l < LNUM; l++) {
        hgemm_s4_kernel<0,0,1><<<grid_qkv, 128, SMQ4>>>(          // 3 (l=0)
            hh, hl, wqh + (size_t)l * 3 * CC * CC, wql + (size_t)l * 3 * CC * CC,
            bqkv + (size_t)l * 3 * CC, nullptr, qvh, qvl, 3 * CC, CC);
        attn_hmma_kernel<<<grid_attn, 128, ASMEM>>>(qvh, qvl, ath, atl);
        if (l == 0) {
            convert_w2_kernel<<<dim3(CC / 32, FFF / 32, 2 * LNUM), cb>>>(
                W2a, W2b, w2ah, w2al, w2bh, w2bl, FFF, CC);
        }
        hgemm_s4_kernel<1,0,1><<<grid_ffn1, 128, SMQ4>>>(
            ath, atl, w1ah + (size_t)l * CC * FFF, w1al + (size_t)l * CC * FFF,
            b1a + (size_t)l * FFF, nullptr, mih, mil, FFF, CC);
        hgemm_s4_pk_kernel<<<grid_ffn2, 128, SMQ4>>>(
            mih, mil, w2ah + (size_t)l * CC * FFF, w2al + (size_t)l * CC * FFF,
            part, BT, CC, FFF);
        ln_res2_kernel<<<BT, 256>>>(part, b2a + (size_t)l * CC,
                                    g1 + (size_t)l * CC,
                                    beta1 + (size_t)l * CC, h, hh, hl);
        hgemm_s4_kernel<1,0,1><<<grid_ffn1, 128, SMQ4>>>(
            hh, hl, w1bh + (size_t)l * CC * FFF, w1bl + (size_t)l * CC * FFF,
            b1b + (size_t)l * FFF, nullptr, mih, mil, FFF, CC);
        hgemm_s4_pk_kernel<<<grid_ffn2, 128, SMQ4>>>(
            mih, mil, w2bh + (size_t)l * CC * FFF, w2bl + (size_t)l * CC * FFF,
            part, BT, CC, FFF);
        ln_res2_kernel<<<BT, 256>>>(part, b2b + (size_t)l * CC,
                                    g2 + (size_t)l * CC,
                                    beta2 + (size_t)l * CC, h, hh, hl);
    }

    convert_w_kernel<<<dim3(VV / 32, CC / 32, 1), cb>>>(lmW, lmh, lml, CC, VV);
    hgemm_s4_kernel<0,1,0><<<grid_lm, 128, SMQ4>>>(
        hh, hl, lmh, lml, lmb, out, nullptr, nullptr, VV, CC);
}